// round 12
// baseline (speedup 1.0000x reference)
#include <cuda_runtime.h>
#include <cuda_fp16.h>
#include <math.h>
#include <stdint.h>

#define Bc 4
#define Sc 1024
#define Dc 512
#define Hc 8
#define DHc 64
#define DIc 2048
#define Lc 12
#define Vc 10000
#define M_ROWS (Bc*Sc)   /* 4096 */
#define QKVSTR (3*Dc)    /* 1536 */

// ---------------- scratch (no allocations allowed) ----------------
__device__ float  g_h   [M_ROWS*Dc];
__device__ __half g_ht  [M_ROWS*Dc];
__device__ __half g_qkv [M_ROWS*QKVSTR];
__device__ __half g_aot [M_ROWS*Dc];
__device__ float  g_tmp [M_ROWS*Dc];
__device__ __half g_fft [M_ROWS*DIc];
__device__ __half g_wqkv[Lc*QKVSTR*Dc];
__device__ __half g_wo_t[Lc*Dc*Dc];
__device__ __half g_w1_t[Lc*DIc*Dc];
__device__ __half g_w2_t[Lc*Dc*DIc];
__device__ __half g_we_t[Vc*Dc];

// ---------------- helpers ----------------------------------------------------
__device__ __forceinline__ void cp16(void* smem, const void* g, int srcBytes) {
    uint32_t s = (uint32_t)__cvta_generic_to_shared(smem);
    asm volatile("cp.async.cg.shared.global [%0], [%1], 16, %2;\n"
                 :: "r"(s), "l"(g), "r"(srcBytes));
}

__device__ __forceinline__ void mma_f16(float c[4],
    uint32_t a0, uint32_t a1, uint32_t a2, uint32_t a3,
    uint32_t b0, uint32_t b1)
{
    asm volatile(
        "mma.sync.aligned.m16n8k16.row.col.f32.f16.f16.f32 "
        "{%0,%1,%2,%3}, {%4,%5,%6,%7}, {%8,%9}, {%0,%1,%2,%3};"
        : "+f"(c[0]), "+f"(c[1]), "+f"(c[2]), "+f"(c[3])
        : "r"(a0), "r"(a1), "r"(a2), "r"(a3), "r"(b0), "r"(b1));
}

__device__ __forceinline__ void ldsm_x4(uint32_t& r0, uint32_t& r1,
                                        uint32_t& r2, uint32_t& r3, uint32_t addr) {
    asm volatile("ldmatrix.sync.aligned.m8n8.x4.shared.b16 {%0,%1,%2,%3}, [%4];"
                 : "=r"(r0), "=r"(r1), "=r"(r2), "=r"(r3) : "r"(addr));
}

__device__ __forceinline__ void ldsm_x2_trans(uint32_t& r0, uint32_t& r1, uint32_t addr) {
    asm volatile("ldmatrix.sync.aligned.m8n8.x2.trans.shared.b16 {%0,%1}, [%2];"
                 : "=r"(r0), "=r"(r1) : "r"(addr));
}

// ---------------- weight preconversion (vectorized) ---------------------------
__global__ void pack_qkv_w8(const float* __restrict__ Wq, const float* __restrict__ Wkv,
                            __half* __restrict__ dst) {
    int i = blockIdx.x * blockDim.x + threadIdx.x;
    const int NC8 = Dc / 8;
    if (i >= Lc * QKVSTR * NC8) return;
    int c8 = (i % NC8) * 8;
    int r  = (i / NC8) % QKVSTR;
    int l  = i / (NC8 * QKVSTR);
    const float* src;
    float sc;
    if (r < Dc) { src = Wq  + ((size_t)l * Dc + r) * Dc + c8;              sc = 0.125f; }
    else        { src = Wkv + ((size_t)l * 2 * Dc + (r - Dc)) * Dc + c8;   sc = 1.f; }
    float4 x = *(const float4*)src;
    float4 y = *(const float4*)(src + 4);
    __half2 o[4];
    o[0] = __floats2half2_rn(x.x * sc, x.y * sc);
    o[1] = __floats2half2_rn(x.z * sc, x.w * sc);
    o[2] = __floats2half2_rn(y.x * sc, y.y * sc);
    o[3] = __floats2half2_rn(y.z * sc, y.w * sc);
    *(uint4*)&dst[(size_t)i * 8] = *(uint4*)o;
}

__global__ void cvt_w8(const float* __restrict__ src, __half* __restrict__ dst, int n8) {
    int i = blockIdx.x * blockDim.x + threadIdx.x;
    if (i >= n8) return;
    float4 x = *(const float4*)(src + (size_t)i * 8);
    float4 y = *(const float4*)(src + (size_t)i * 8 + 4);
    __half2 o[4];
    o[0] = __floats2half2_rn(x.x, x.y);
    o[1] = __floats2half2_rn(x.z, x.w);
    o[2] = __floats2half2_rn(y.x, y.y);
    o[3] = __floats2half2_rn(y.z, y.w);
    *(uint4*)&dst[(size_t)i * 8] = *(uint4*)o;
}

// ---------------- embedding (4 elems/thread) ----------------
__global__ void embed_kernel(const int* __restrict__ data,
                             const float* __restrict__ we,
                             const float* __restrict__ pe,
                             float* __restrict__ h, __half* __restrict__ ht) {
    int i = blockIdx.x * blockDim.x + threadIdx.x;
    if (i >= M_ROWS * Dc / 4) return;
    int d4  = (i % (Dc / 4)) * 4;
    int row = i / (Dc / 4);
    int s   = row % Sc;
    int tok = data[row];
    float4 a = *(const float4*)(we + (size_t)tok * Dc + d4);
    float4 p = *(const float4*)(pe + (size_t)s   * Dc + d4);
    float4 v = make_float4(a.x + p.x, a.y + p.y, a.z + p.z, a.w + p.w);
    *(float4*)&h[(size_t)row * Dc + d4] = v;
    __half2 o[2];
    o[0] = __floats2half2_rn(v.x, v.y);
    o[1] = __floats2half2_rn(v.z, v.w);
    *(uint2*)&ht[(size_t)row * Dc + d4] = *(uint2*)o;
}

// ============ tgemm64: TBM=64, TBN=128, 3-stage pipeline, 1 sync/iter =========
#define T2M 64
#define T2N 128
#define T2K 32
#define TP 40

__global__ __launch_bounds__(256) void tgemm64_kernel(
    const __half* __restrict__ A, const __half* __restrict__ W,
    const float* __restrict__ bias, const float* __restrict__ res,
    void* __restrict__ Cv, int M, int N, int K, int doRelu, int outMode)
{
    __shared__ __align__(16) __half As[3][T2M][TP];
    __shared__ __align__(16) __half Bs[3][T2N][TP];

    const int tid  = threadIdx.x;
    const int lane = tid & 31;
    const int warp = tid >> 5;
    const int wm   = warp >> 2;
    const int wn   = warp & 3;
    const int bm   = blockIdx.y * T2M;
    const int bn   = blockIdx.x * T2N;

    const uint32_t asBase = (uint32_t)__cvta_generic_to_shared(&As[0][0][0]);
    const uint32_t bsBase = (uint32_t)__cvta_generic_to_shared(&Bs[0][0][0]);

    float acc[2][4][4];
    #pragma unroll
    for (int i = 0; i < 2; i++)
        #pragma unroll
        for (int j = 0; j < 4; j++)
            #pragma unroll
            for (int t = 0; t < 4; t++) acc[i][j][t] = 0.f;

    const int KT = K / T2K;
    const int rA  = tid >> 2, hA = (tid & 3) * 8;

    #pragma unroll
    for (int s = 0; s < 2; s++) {
        int k0 = s * T2K;
        cp16(&As[s][rA][hA], A + (size_t)(bm + rA) * K + k0 + hA, 16);
        #pragma unroll
        for (int p = 0; p < 2; p++) {
            int c = tid + p * 256;
            int r = c >> 2, hf = (c & 3) * 8;
            cp16(&Bs[s][r][hf], W + (size_t)(bn + r) * K + k0 + hf, 16);
        }
        asm volatile("cp.async.commit_group;\n");
    }

    const int r8  = lane & 7;
    const int sel = lane >> 3;

    for (int t = 0; t < KT; t++) {
        asm volatile("cp.async.wait_group 1;\n");
        __syncthreads();

        {
            int tp = t + 2;
            if (tp < KT) {
                int sb = tp % 3;
                int k0 = tp * T2K;
                cp16(&As[sb][rA][hA], A + (size_t)(bm + rA) * K + k0 + hA, 16);
                #pragma unroll
                for (int p = 0; p < 2; p++) {
                    int c = tid + p * 256;
                    int r = c >> 2, hf = (c & 3) * 8;
                    cp16(&Bs[sb][r][hf], W + (size_t)(bn + r) * K + k0 + hf, 16);
                }
            }
            asm volatile("cp.async.commit_group;\n");
        }

        const int buf = t % 3;
        #pragma unroll
        for (int ks = 0; ks < 2; ks++) {
            const int kb = ks * 16;
            uint32_t af[2][4], bf[4][2];
            #pragma unroll
            for (int mi = 0; mi < 2; mi++) {
                int row  = wm * 32 + mi * 16 + r8 + ((sel & 1) << 3);
                int colh = kb + ((sel >> 1) << 3);
                uint32_t addr = asBase + (((buf * T2M + row) * TP + colh) << 1);
                ldsm_x4(af[mi][0], af[mi][1], af[mi][2], af[mi][3], addr);
            }
            #pragma unroll
            for (int nj = 0; nj < 2; nj++) {
                int row  = wn * 32 + nj * 16 + r8 + ((sel >> 1) << 3);
                int colh = kb + ((sel & 1) << 3);
                uint32_t addr = bsBase + (((buf * T2N + row) * TP + colh) << 1);
                ldsm_x4(bf[nj*2][0], bf[nj*2][1], bf[nj*2+1][0], bf[nj*2+1][1], addr);
            }
            #pragma unroll
            for (int mi = 0; mi < 2; mi++)
                #pragma unroll
                for (int ni = 0; ni < 4; ni++)
                    mma_f16(acc[mi][ni], af[mi][0], af[mi][1], af[mi][2], af[mi][3],
                            bf[ni][0], bf[ni][1]);
        }
    }

    const int lr = lane >> 2;
    const int lc = (lane & 3) * 2;
    #pragma unroll
    for (int mi = 0; mi < 2; mi++) {
        int r0 = bm + wm * 32 + mi * 16 + lr;
        #pragma unroll
        for (int ni = 0; ni < 4; ni++) {
            int c0 = bn + wn * 32 + ni * 8 + lc;
            float v0 = acc[mi][ni][0], v1 = acc[mi][ni][1];
            float v2 = acc[mi][ni][2], v3 = acc[mi][ni][3];
            if (bias) {
                float b0 = bias[c0], b1 = bias[c0 + 1];
                v0 += b0; v1 += b1; v2 += b0; v3 += b1;
            }
            if (res) {
                v0 += res[(size_t)r0 * N + c0];
                v1 += res[(size_t)r0 * N + c0 + 1];
                v2 += res[(size_t)(r0 + 8) * N + c0];
                v3 += res[(size_t)(r0 + 8) * N + c0 + 1];
            }
            if (doRelu) {
                v0 = fmaxf(v0, 0.f); v1 = fmaxf(v1, 0.f);
                v2 = fmaxf(v2, 0.f); v3 = fmaxf(v3, 0.f);
            }
            if (outMode == 0) {
                float* C = (float*)Cv;
                *(float2*)&C[(size_t)r0 * N + c0]       = make_float2(v0, v1);
                *(float2*)&C[(size_t)(r0 + 8) * N + c0] = make_float2(v2, v3);
            } else {
                __half* C = (__half*)Cv;
                *(__half2*)&C[(size_t)r0 * N + c0]       = __floats2half2_rn(v0, v1);
                *(__half2*)&C[(size_t)(r0 + 8) * N + c0] = __floats2half2_rn(v2, v3);
            }
        }
    }
}

// ============ tgemm128: proven 128x128 TBK=32 kernel (logits) ================
#define TBM 128
#define TBN 128
#define TBK 32

__global__ __launch_bounds__(256) void tgemm_kernel(
    const __half* __restrict__ A, const __half* __restrict__ W,
    const float* __restrict__ bias, const float* __restrict__ res,
    void* __restrict__ Cv, int M, int N, int K, int doRelu, int outMode)
{
    __shared__ __align__(16) __half As[2][TBM][TP];
    __shared__ __align__(16) __half Bs[2][TBN][TP];

    const int tid  = threadIdx.x;
    const int lane = tid & 31;
    const int warp = tid >> 5;
    const int wm   = warp >> 2;
    const int wn   = warp & 3;
    const int bm   = blockIdx.y * TBM;
    const int bn   = blockIdx.x * TBN;

    const uint32_t asBase = (uint32_t)__cvta_generic_to_shared(&As[0][0][0]);
    const uint32_t bsBase = (uint32_t)__cvta_generic_to_shared(&Bs[0][0][0]);

    float acc[4][4][4];
    #pragma unroll
    for (int i = 0; i < 4; i++)
        #pragma unroll
        for (int j = 0; j < 4; j++)
            #pragma unroll
            for (int t = 0; t < 4; t++) acc[i][j][t] = 0.f;

    const int KT = K / TBK;

    #pragma unroll
    for (int p = 0; p < 2; p++) {
        int c = tid + p * 256;
        int r = c >> 2, hoff = (c & 3) * 8;
        cp16(&As[0][r][hoff], A + (size_t)(bm + r) * K + hoff, 16);
        int gn = bn + r;
        int ok = (gn < N) ? 16 : 0;
        int gc = (gn < N) ? gn : (N - 1);
        cp16(&Bs[0][r][hoff], W + (size_t)gc * K + hoff, ok);
    }
    asm volatile("cp.async.commit_group;\n");

    const int r8  = lane & 7;
    const int sel = lane >> 3;

    for (int t = 0; t < KT; t++) {
        asm volatile("cp.async.wait_group 0;\n");
        __syncthreads();

        if (t + 1 < KT) {
            int nb = (t + 1) & 1;
            int k0 = (t + 1) * TBK;
            #pragma unroll
            for (int p = 0; p < 2; p++) {
                int c = tid + p * 256;
                int r = c >> 2, hoff = (c & 3) * 8;
                cp16(&As[nb][r][hoff], A + (size_t)(bm + r) * K + k0 + hoff, 16);
                int gn = bn + r;
                int ok = (gn < N) ? 16 : 0;
                int gc = (gn < N) ? gn : (N - 1);
                cp16(&Bs[nb][r][hoff], W + (size_t)gc * K + k0 + hoff, ok);
            }
            asm volatile("cp.async.commit_group;\n");
        }

        const int buf = t & 1;
        #pragma unroll
        for (int ks = 0; ks < 2; ks++) {
            const int kb = ks * 16;
            uint32_t af[4][4], bf[4][2];
            #pragma unroll
            for (int mi = 0; mi < 4; mi++) {
                int row  = wm * 64 + mi * 16 + r8 + ((sel & 1) << 3);
                int colh = kb + ((sel >> 1) << 3);
                uint32_t addr = asBase + (((buf * TBM + row) * TP + colh) << 1);
                ldsm_x4(af[mi][0], af[mi][1], af[mi][2], af[mi][3], addr);
            }
            #pragma unroll
            for (int nj = 0; nj < 2; nj++) {
                int row  = wn * 32 + nj * 16 + r8 + ((sel >> 1) << 3);
                int colh = kb + ((sel & 1) << 3);
                uint32_t addr = bsBase + (((buf * TBN + row) * TP + colh) << 1);
                ldsm_x4(bf[nj*2][0], bf[nj*2][1], bf[nj*2+1][0], bf[nj*2+1][1], addr);
            }
            #pragma unroll
            for (int mi = 0; mi < 4; mi++)
                #pragma unroll
                for (int ni = 0; ni < 4; ni++)
                    mma_f16(acc[mi][ni], af[mi][0], af[mi][1], af[mi][2], af[mi][3],
                            bf[ni][0], bf[ni][1]);
        }
        __syncthreads();
    }

    const int lr = lane >> 2;
    const int lc = (lane & 3) * 2;
    #pragma unroll
    for (int mi = 0; mi < 4; mi++) {
        int r0 = bm + wm * 64 + mi * 16 + lr;
        #pragma unroll
        for (int ni = 0; ni < 4; ni++) {
            int c0 = bn + wn * 32 + ni * 8 + lc;
            if (c0 >= N) continue;
            float v0 = acc[mi][ni][0], v1 = acc[mi][ni][1];
            float v2 = acc[mi][ni][2], v3 = acc[mi][ni][3];
            if (bias) {
                float b0 = bias[c0], b1 = bias[c0 + 1];
                v0 += b0; v1 += b1; v2 += b0; v3 += b1;
            }
            if (res) {
                v0 += res[(size_t)r0 * N + c0];
                v1 += res[(size_t)r0 * N + c0 + 1];
                v2 += res[(size_t)(r0 + 8) * N + c0];
                v3 += res[(size_t)(r0 + 8) * N + c0 + 1];
            }
            if (doRelu) {
                v0 = fmaxf(v0, 0.f); v1 = fmaxf(v1, 0.f);
                v2 = fmaxf(v2, 0.f); v3 = fmaxf(v3, 0.f);
            }
            if (outMode == 0) {
                float* C = (float*)Cv;
                *(float2*)&C[(size_t)r0 * N + c0]       = make_float2(v0, v1);
                *(float2*)&C[(size_t)(r0 + 8) * N + c0] = make_float2(v2, v3);
            } else {
                __half* C = (__half*)Cv;
                *(__half2*)&C[(size_t)r0 * N + c0]       = __floats2half2_rn(v0, v1);
                *(__half2*)&C[(size_t)(r0 + 8) * N + c0] = __floats2half2_rn(v2, v3);
            }
        }
    }
}

// ---------------- fp16 flash attention: 128q x 64k tiles, 8 warps -------------
#define APH 72
#define FATTN_SMEM ((128 + 128 + 128 + 128) * APH * 2)

extern __shared__ __half attn_smem[];

__global__ __launch_bounds__(256) void fattn_tc(
    const __half* __restrict__ Q, const __half* __restrict__ Kb,
    const __half* __restrict__ Vb, __half* __restrict__ O)
{
    __half* Qs = attn_smem;               // [128][APH]
    __half* Ks = Qs + 128 * APH;          // 2 x [64][APH]
    __half* Vk = Ks + 2 * 64 * APH;       // 2 x [64][APH]
    __half* Ps = Vk + 2 * 64 * APH;       // [128][APH]

    const int qt = (gridDim.x - 1) - blockIdx.x;
    const int h  = blockIdx.y, b = blockIdx.z;
    const int q0 = qt * 128;
    const int tid  = threadIdx.x;
    const int lane = tid & 31;
    const int warp = tid >> 5;            // 0..7

    const int OST = Hc * DHc;

    const int r0  = warp * 16 + (lane >> 2);    // 0..127
    const int kh  = (lane & 3) * 2;
    const int ls4 = lane >> 2;

    // load Q tile: 128 rows x 128B = 1024 x 16B chunks over 256 threads
    #pragma unroll
    for (int p = 0; p < 4; p++) {
        int c = tid + p * 256;
        int r = c >> 3, d8 = (c & 7) * 8;
        float4 v = *(const float4*)(Q + (size_t)(b * Sc + q0 + r) * QKVSTR + h * DHc + d8);
        *(float4*)&Qs[r * APH + d8] = v;
    }

    float o_acc[8][4];
    #pragma unroll
    for (int n = 0; n < 8; n++)
        #pragma unroll
        for (int t = 0; t < 4; t++) o_acc[n][t] = 0.f;
    float m0 = -1e30f, m1 = -1e30f, l0 = 0.f, l1 = 0.f;

    const int nt = 2 * qt + 2;            // kv tiles of 64 covering [0, q0+128)
    const size_t kvrow0 = (size_t)(b * Sc) * QKVSTR + h * DHc;

    // prologue: kv tile 0 (512 chunks each over 256 threads)
    #pragma unroll
    for (int p = 0; p < 2; p++) {
        int c = tid + p * 256;
        int r = c >> 3, d8 = (c & 7) * 8;
        cp16(&Ks[r * APH + d8], Kb + kvrow0 + (size_t)r * QKVSTR + d8, 16);
        cp16(&Vk[r * APH + d8], Vb + kvrow0 + (size_t)r * QKVSTR + d8, 16);
    }
    asm volatile("cp.async.commit_group;\n");

    for (int kt = 0; kt < nt; kt++) {
        asm volatile("cp.async.wait_group 0;\n");
        __syncthreads();

        const int buf = kt & 1;
        if (kt + 1 < nt) {
            const int nb = buf ^ 1;
            const size_t base = kvrow0 + (size_t)(kt + 1) * 64 * QKVSTR;
            #pragma unroll
            for (int p = 0; p < 2; p++) {
                int c = tid + p * 256;
                int r = c >> 3, d8 = (c & 7) * 8;
                cp16(&Ks[nb * 64 * APH + r * APH + d8], Kb + base + (size_t)r * QKVSTR + d8, 16);
                cp16(&Vk[nb * 64 * APH + r * APH + d8], Vb + base + (size_t)r * QKVSTR + d8, 16);
            }
        }
        asm volatile("cp.async.commit_group;\n");

        const __half* Kt = Ks + buf * 64 * APH;
        const __half* Vt = Vk + buf * 64 * APH;

        float sacc[8][4];
        #pragma unroll
        for (int n = 0; n < 8; n++)
            #pragma unroll
            for (int t = 0; t < 4; t++) sacc[n][t] = 0.f;

        #pragma unroll
        for (int ks = 0; ks < 4; ks++) {
            const int kb = ks * 16;
            uint32_t a0 = *(const uint32_t*)&Qs[ r0      * APH + kb + kh];
            uint32_t a1 = *(const uint32_t*)&Qs[(r0 + 8) * APH + kb + kh];
            uint32_t a2 = *(const uint32_t*)&Qs[ r0      * APH + kb + kh + 8];
            uint32_t a3 = *(const uint32_t*)&Qs[(r0 + 8) * APH + kb + kh + 8];
            #pragma unroll
            for (int n = 0; n < 8; n++) {
                const int nr = n * 8 + ls4;
                uint32_t b0 = *(const uint32_t*)&Kt[nr * APH + kb + kh];
                uint32_t b1 = *(const uint32_t*)&Kt[nr * APH + kb + kh + 8];
                mma_f16(sacc[n], a0, a1, a2, a3, b0, b1);
            }
        }

        // causal mask: kv col (kt*64 + c) > q row (q0 + r)   <=>  koff + c > r
        const int koff = kt * 64 - 128 * qt;    // -inf..64; only last two tiles matter
        if (koff > -64) {
            #pragma unroll
            for (int n = 0; n < 8; n++) {
                const int c0 = koff + n * 8 + (lane & 3) * 2;
                if (c0     > r0)     sacc[n][0] = -1e30f;
                if (c0 + 1 > r0)     sacc[n][1] = -1e30f;
                if (c0     > r0 + 8) sacc[n][2] = -1e30f;
                if (c0 + 1 > r0 + 8) sacc[n][3] = -1e30f;
            }
        }

        float mx0 = -1e30f, mx1 = -1e30f;
        #pragma unroll
        for (int n = 0; n < 8; n++) {
            mx0 = fmaxf(mx0, fmaxf(sacc[n][0], sacc[n][1]));
            mx1 = fmaxf(mx1, fmaxf(sacc[n][2], sacc[n][3]));
        }
        mx0 = fmaxf(mx0, __shfl_xor_sync(0xffffffffu, mx0, 1));
        mx0 = fmaxf(mx0, __shfl_xor_sync(0xffffffffu, mx0, 2));
        mx1 = fmaxf(mx1, __shfl_xor_sync(0xffffffffu, mx1, 1));
        mx1 = fmaxf(mx1, __shfl_xor_sync(0xffffffffu, mx1, 2));

        const float mn0 = fmaxf(m0, mx0);
        const float mn1 = fmaxf(m1, mx1);
        const float cr0 = __expf(m0 - mn0);
        const float cr1 = __expf(m1 - mn1);
        float s0 = 0.f, s1 = 0.f;
        #pragma unroll
        for (int n = 0; n < 8; n++) {
            float p00 = __expf(sacc[n][0] - mn0);
            float p01 = __expf(sacc[n][1] - mn0);
            float p10 = __expf(sacc[n][2] - mn1);
            float p11 = __expf(sacc[n][3] - mn1);
            s0 += p00 + p01;
            s1 += p10 + p11;
            const int c0 = n * 8 + (lane & 3) * 2;
            *(__half2*)&Ps[ r0      * APH + c0] = __floats2half2_rn(p00, p01);
            *(__half2*)&Ps[(r0 + 8) * APH + c0] = __floats2half2_rn(p10, p11);
        }
        s0 += __shfl_xor_sync(0xffffffffu, s0, 1);
        s0 += __shfl_xor_sync(0xffffffffu, s0, 2);
        s1 += __shfl_xor_sync(0xffffffffu, s1, 1);
        s1 += __shfl_xor_sync(0xffffffffu, s1, 2);

        l0 = l0 * cr0 + s0;  m0 = mn0;
        l1 = l1 * cr1 + s1;  m1 = mn1;
        #pragma unroll
        for (int n = 0; n < 8; n++) {
            o_acc[n][0] *= cr0; o_acc[n][1] *= cr0;
            o_acc[n][2] *= cr1; o_acc[n][3] *= cr1;
        }
        __syncwarp();

        #pragma unroll
        for (int ks = 0; ks < 4; ks++) {
            const int kb = ks * 16;
            uint32_t a0 = *(const uint32_t*)&Ps[ r0      * APH + kb + kh];
            uint32_t a1 = *(const uint32_t*)&Ps[(r0 + 8) * APH + kb + kh];
            uint32_t a2 = *(const uint32_t*)&Ps[ r0      * APH + kb + kh + 8];
            uint32_t a3 = *(const uint32_t*)&Ps[(r0 + 8) * APH + kb + kh + 8];
            uint32_t base = (uint32_t)__cvta_generic_to_shared(
                                &Vt[(kb + (lane & 15)) * APH]);
            #pragma unroll
            for (int n = 0; n < 8; n++) {
                uint32_t b0, b1;
                ldsm_x2_trans(b0, b1, base + n * 16);
                mma_f16(o_acc[n], a0, a1, a2, a3, b0, b1);
            }
        }
    }

    const float inv0 = 1.f / l0;
    const float inv1 = 1.f / l1;
    #pragma unroll
    for (int n = 0; n < 8; n++) {
        const int c0 = n * 8 + (lane & 3) * 2;
        size_t o0 = (size_t)(b * Sc + q0 + r0)     * OST + h * DHc + c0;
        size_t o1 = (size_t)(b * Sc + q0 + r0 + 8) * OST + h * DHc + c0;
        *(__half2*)&O[o0] = __floats2half2_rn(o_acc[n][0] * inv0, o_acc[n][1] * inv0);
        *(__half2*)&O[o1] = __floats2half2_rn(o_acc[n][2] * inv1, o_acc[n][3] * inv1);
    }
}

// ---------------- LayerNorm over D=512 (single-pass reduction) ----------------
__global__ void ln_kernel(const float* __restrict__ X, const float* __restrict__ g,
                          const float* __restrict__ bta, float* __restrict__ Y,
                          __half* __restrict__ Yt) {
    int row = blockIdx.x;
    const float* x = X + (size_t)row * Dc;
    float*  y  = Y  + (size_t)row * Dc;
    __half* yt = Yt + (size_t)row * Dc;
    int tid = threadIdx.x;
    int d0  = tid * 4;

    float4 v = *(const float4*)(x + d0);
    float sum = v.x + v.y + v.z + v.w;
    float sq  = v.x*v.x + v.y*v.y + v.z*v.z + v.w*v.w;

    __shared__ float redS[4], redQ[4];
    #pragma unroll
    for (int off = 16; off; off >>= 1) {
        sum += __shfl_xor_sync(0xffffffffu, sum, off);
        sq  += __shfl_xor_sync(0xffffffffu, sq,  off);
    }
    if ((tid & 31) == 0) { redS[tid >> 5] = sum; redQ[tid >> 5] = sq; }
    __syncthreads();
    sum = redS[0] + redS[1] + redS[2] + redS[3];
    sq  = redQ[0] + redQ[1] + redQ[2] + redQ[3];
    float mean = sum * (1.f / Dc);
    float var  = sq * (1.f / Dc) - mean * mean;
    float rstd = rsqrtf(var + 1e-5f);

    float4 gg = *(const float4*)(g + d0);
    float4 bb = *(const float4*)(bta + d0);
    float4 o;
    o.x = (v.x - mean) * rstd * gg.x + bb.x;
    o.y = (v.y - mean) * rstd * gg.y + bb.y;
    o.z = (v.z - mean) * rstd * gg.z + bb.z;
    o.w = (v.w - mean) * rstd * gg.w + bb.w;
    *(float4*)(y + d0) = o;
    __half2 ho[2];
    ho[0] = __floats2half2_rn(o.x, o.y);
    ho[1] = __floats2half2_rn(o.z, o.w);
    *(uint2*)(yt + d0) = *(uint2*)ho;
}

// ---------------- launch ----------------------------------------------------
extern "C" void kernel_launch(void* const* d_in, const int* in_sizes, int n_in,
                              void* d_out, int out_size) {
    const int*   data = (const int*)  d_in[0];
    const float* we   = (const float*)d_in[1];
    const float* pe   = (const float*)d_in[2];
    const float* Wq   = (const float*)d_in[3];
    const float* Wkv  = (const float*)d_in[4];
    const float* Wo   = (const float*)d_in[5];
    const float* g1   = (const float*)d_in[6];
    const float* bl1  = (const float*)d_in[7];
    const float* W1   = (const float*)d_in[8];
    const float* bf1  = (const float*)d_in[9];
    const float* W2   = (const float*)d_in[10];
    const float* bf2  = (const float*)d_in[11];
    const float* g2   = (const float*)d_in[12];
    const float* bl2  = (const float*)d_in[13];
    const float* outb = (const float*)d_in[14];
    float* out = (float*)d_out;

    float *h, *tmp;
    __half *ht, *qkv, *aot, *fft;
    __half *wqkv, *wo_t, *w1_t, *w2_t, *we_t;
    cudaGetSymbolAddress((void**)&h,    g_h);
    cudaGetSymbolAddress((void**)&ht,   g_ht);
    cudaGetSymbolAddress((void**)&qkv,  g_qkv);
    cudaGetSymbolAddress((void**)&aot,  g_aot);
    cudaGetSymbolAddress((void**)&tmp,  g_tmp);
    cudaGetSymbolAddress((void**)&fft,  g_fft);
    cudaGetSymbolAddress((void**)&wqkv, g_wqkv);
    cudaGetSymbolAddress((void**)&wo_t, g_wo_t);
    cudaGetSymbolAddress((void**)&w1_t, g_w1_t);
    cudaGetSymbolAddress((void**)&w2_t, g_w2_t);
    cudaGetSymbolAddress((void**)&we_t, g_we_t);

    cudaFuncSetAttribute(fattn_tc, cudaFuncAttributeMaxDynamicSharedMemorySize, FATTN_SMEM);

    {
        int n8;
        n8 = Lc * QKVSTR * Dc / 8;  pack_qkv_w8<<<(n8 + 255)/256, 256>>>(Wq, Wkv, wqkv);
        n8 = Lc * Dc * Dc / 8;      cvt_w8<<<(n8 + 255)/256, 256>>>(Wo, wo_t, n8);
        n8 = Lc * DIc * Dc / 8;     cvt_w8<<<(n8 + 255)/256, 256>>>(W1, w1_t, n8);
        n8 = Lc * Dc * DIc / 8;     cvt_w8<<<(n8 + 255)/256, 256>>>(W2, w2_t, n8);
        n8 = Vc * Dc / 8;           cvt_w8<<<(n8 + 255)/256, 256>>>(we, we_t, n8);
    }

    embed_kernel<<<(M_ROWS*Dc/4 + 255)/256, 256>>>(data, we, pe, h, ht);

    dim3 g64D  ( Dc/128,     M_ROWS/64);
    dim3 g64QKV( QKVSTR/128, M_ROWS/64);
    dim3 g64DI ( DIc/128,    M_ROWS/64);
    dim3 gsV   ((Vc + 127)/128, M_ROWS/128);
    dim3 gsA   (Sc/128, Hc, Bc);

    for (int l = 0; l < Lc; l++) {
        tgemm64_kernel<<<g64QKV, 256>>>(ht, wqkv + (size_t)l*QKVSTR*Dc, nullptr, nullptr,
                                        qkv, M_ROWS, QKVSTR, Dc, 0, 1);

        fattn_tc<<<gsA, 256, FATTN_SMEM>>>(qkv, qkv + Dc, qkv + 2*Dc, aot);

        tgemm64_kernel<<<g64D, 256>>>(aot, wo_t + (size_t)l*Dc*Dc, nullptr, h, tmp,
                                      M_ROWS, Dc, Dc, 0, 0);
        ln_kernel<<<M_ROWS, 128>>>(tmp, g1 + (size_t)l*Dc, bl1 + (size_t)l*Dc, h, ht);

        tgemm64_kernel<<<g64DI, 256>>>(ht, w1_t + (size_t)l*DIc*Dc, bf1 + (size_t)l*DIc, nullptr,
                                       fft, M_ROWS, DIc, Dc, 1, 1);
        tgemm64_kernel<<<g64D, 256>>>(fft, w2_t + (size_t)l*Dc*DIc, bf2 + (size_t)l*Dc, h,
                                      tmp, M_ROWS, Dc, DIc, 0, 0);
        ln_kernel<<<M_ROWS, 128>>>(tmp, g2 + (size_t)l*Dc, bl2 + (size_t)l*Dc, h, ht);
    }

    tgemm_kernel<<<gsV, 256>>>(ht, we_t, outb, nullptr, out, M_ROWS, Vc, Dc, 0, 0);
}

// round 13
// speedup vs baseline: 1.0216x; 1.0216x over previous
#include <cuda_runtime.h>
#include <cuda_fp16.h>
#include <math.h>
#include <stdint.h>

#define Bc 4
#define Sc 1024
#define Dc 512
#define Hc 8
#define DHc 64
#define DIc 2048
#define Lc 12
#define Vc 10000
#define M_ROWS (Bc*Sc)   /* 4096 */
#define QKVSTR (3*Dc)    /* 1536 */

// ---------------- scratch (no allocations allowed) ----------------
__device__ float  g_h   [M_ROWS*Dc];
__device__ __half g_ht  [M_ROWS*Dc];
__device__ __half g_qkv [M_ROWS*QKVSTR];
__device__ __half g_aot [M_ROWS*Dc];
__device__ float  g_tmp [M_ROWS*Dc];
__device__ __half g_fft [M_ROWS*DIc];
__device__ __half g_wqkv[Lc*QKVSTR*Dc];
__device__ __half g_wo_t[Lc*Dc*Dc];
__device__ __half g_w1_t[Lc*DIc*Dc];
__device__ __half g_w2_t[Lc*Dc*DIc];
__device__ __half g_we_t[Vc*Dc];

// ---------------- helpers ----------------------------------------------------
__device__ __forceinline__ void cp16(void* smem, const void* g, int srcBytes) {
    uint32_t s = (uint32_t)__cvta_generic_to_shared(smem);
    asm volatile("cp.async.cg.shared.global [%0], [%1], 16, %2;\n"
                 :: "r"(s), "l"(g), "r"(srcBytes));
}

__device__ __forceinline__ void mma_f16(float c[4],
    uint32_t a0, uint32_t a1, uint32_t a2, uint32_t a3,
    uint32_t b0, uint32_t b1)
{
    asm volatile(
        "mma.sync.aligned.m16n8k16.row.col.f32.f16.f16.f32 "
        "{%0,%1,%2,%3}, {%4,%5,%6,%7}, {%8,%9}, {%0,%1,%2,%3};"
        : "+f"(c[0]), "+f"(c[1]), "+f"(c[2]), "+f"(c[3])
        : "r"(a0), "r"(a1), "r"(a2), "r"(a3), "r"(b0), "r"(b1));
}

__device__ __forceinline__ void ldsm_x4(uint32_t& r0, uint32_t& r1,
                                        uint32_t& r2, uint32_t& r3, uint32_t addr) {
    asm volatile("ldmatrix.sync.aligned.m8n8.x4.shared.b16 {%0,%1,%2,%3}, [%4];"
                 : "=r"(r0), "=r"(r1), "=r"(r2), "=r"(r3) : "r"(addr));
}

__device__ __forceinline__ void ldsm_x2_trans(uint32_t& r0, uint32_t& r1, uint32_t addr) {
    asm volatile("ldmatrix.sync.aligned.m8n8.x2.trans.shared.b16 {%0,%1}, [%2];"
                 : "=r"(r0), "=r"(r1) : "r"(addr));
}

__device__ __forceinline__ uint32_t f2h2(float a, float b) {
    __half2 h = __floats2half2_rn(a, b);
    return *(uint32_t*)&h;
}

// ---------------- weight preconversion (vectorized) ---------------------------
__global__ void pack_qkv_w8(const float* __restrict__ Wq, const float* __restrict__ Wkv,
                            __half* __restrict__ dst) {
    int i = blockIdx.x * blockDim.x + threadIdx.x;
    const int NC8 = Dc / 8;
    if (i >= Lc * QKVSTR * NC8) return;
    int c8 = (i % NC8) * 8;
    int r  = (i / NC8) % QKVSTR;
    int l  = i / (NC8 * QKVSTR);
    const float* src;
    float sc;
    if (r < Dc) { src = Wq  + ((size_t)l * Dc + r) * Dc + c8;              sc = 0.125f; }
    else        { src = Wkv + ((size_t)l * 2 * Dc + (r - Dc)) * Dc + c8;   sc = 1.f; }
    float4 x = *(const float4*)src;
    float4 y = *(const float4*)(src + 4);
    __half2 o[4];
    o[0] = __floats2half2_rn(x.x * sc, x.y * sc);
    o[1] = __floats2half2_rn(x.z * sc, x.w * sc);
    o[2] = __floats2half2_rn(y.x * sc, y.y * sc);
    o[3] = __floats2half2_rn(y.z * sc, y.w * sc);
    *(uint4*)&dst[(size_t)i * 8] = *(uint4*)o;
}

__global__ void cvt_w8(const float* __restrict__ src, __half* __restrict__ dst, int n8) {
    int i = blockIdx.x * blockDim.x + threadIdx.x;
    if (i >= n8) return;
    float4 x = *(const float4*)(src + (size_t)i * 8);
    float4 y = *(const float4*)(src + (size_t)i * 8 + 4);
    __half2 o[4];
    o[0] = __floats2half2_rn(x.x, x.y);
    o[1] = __floats2half2_rn(x.z, x.w);
    o[2] = __floats2half2_rn(y.x, y.y);
    o[3] = __floats2half2_rn(y.z, y.w);
    *(uint4*)&dst[(size_t)i * 8] = *(uint4*)o;
}

// ---------------- embedding (4 elems/thread) ----------------
__global__ void embed_kernel(const int* __restrict__ data,
                             const float* __restrict__ we,
                             const float* __restrict__ pe,
                             float* __restrict__ h, __half* __restrict__ ht) {
    int i = blockIdx.x * blockDim.x + threadIdx.x;
    if (i >= M_ROWS * Dc / 4) return;
    int d4  = (i % (Dc / 4)) * 4;
    int row = i / (Dc / 4);
    int s   = row % Sc;
    int tok = data[row];
    float4 a = *(const float4*)(we + (size_t)tok * Dc + d4);
    float4 p = *(const float4*)(pe + (size_t)s   * Dc + d4);
    float4 v = make_float4(a.x + p.x, a.y + p.y, a.z + p.z, a.w + p.w);
    *(float4*)&h[(size_t)row * Dc + d4] = v;
    __half2 o[2];
    o[0] = __floats2half2_rn(v.x, v.y);
    o[1] = __floats2half2_rn(v.z, v.w);
    *(uint2*)&ht[(size_t)row * Dc + d4] = *(uint2*)o;
}

// ============ tgemm64: TBM=64, TBN=128, 3-stage pipeline, 1 sync/iter =========
#define T2M 64
#define T2N 128
#define T2K 32
#define TP 40

__global__ __launch_bounds__(256) void tgemm64_kernel(
    const __half* __restrict__ A, const __half* __restrict__ W,
    const float* __restrict__ bias, const float* __restrict__ res,
    void* __restrict__ Cv, int M, int N, int K, int doRelu, int outMode)
{
    __shared__ __align__(16) __half As[3][T2M][TP];
    __shared__ __align__(16) __half Bs[3][T2N][TP];

    const int tid  = threadIdx.x;
    const int lane = tid & 31;
    const int warp = tid >> 5;
    const int wm   = warp >> 2;
    const int wn   = warp & 3;
    const int bm   = blockIdx.y * T2M;
    const int bn   = blockIdx.x * T2N;

    const uint32_t asBase = (uint32_t)__cvta_generic_to_shared(&As[0][0][0]);
    const uint32_t bsBase = (uint32_t)__cvta_generic_to_shared(&Bs[0][0][0]);

    float acc[2][4][4];
    #pragma unroll
    for (int i = 0; i < 2; i++)
        #pragma unroll
        for (int j = 0; j < 4; j++)
            #pragma unroll
            for (int t = 0; t < 4; t++) acc[i][j][t] = 0.f;

    const int KT = K / T2K;
    const int rA  = tid >> 2, hA = (tid & 3) * 8;

    #pragma unroll
    for (int s = 0; s < 2; s++) {
        int k0 = s * T2K;
        cp16(&As[s][rA][hA], A + (size_t)(bm + rA) * K + k0 + hA, 16);
        #pragma unroll
        for (int p = 0; p < 2; p++) {
            int c = tid + p * 256;
            int r = c >> 2, hf = (c & 3) * 8;
            cp16(&Bs[s][r][hf], W + (size_t)(bn + r) * K + k0 + hf, 16);
        }
        asm volatile("cp.async.commit_group;\n");
    }

    const int r8  = lane & 7;
    const int sel = lane >> 3;

    for (int t = 0; t < KT; t++) {
        asm volatile("cp.async.wait_group 1;\n");
        __syncthreads();

        {
            int tp = t + 2;
            if (tp < KT) {
                int sb = tp % 3;
                int k0 = tp * T2K;
                cp16(&As[sb][rA][hA], A + (size_t)(bm + rA) * K + k0 + hA, 16);
                #pragma unroll
                for (int p = 0; p < 2; p++) {
                    int c = tid + p * 256;
                    int r = c >> 2, hf = (c & 3) * 8;
                    cp16(&Bs[sb][r][hf], W + (size_t)(bn + r) * K + k0 + hf, 16);
                }
            }
            asm volatile("cp.async.commit_group;\n");
        }

        const int buf = t % 3;
        #pragma unroll
        for (int ks = 0; ks < 2; ks++) {
            const int kb = ks * 16;
            uint32_t af[2][4], bf[4][2];
            #pragma unroll
            for (int mi = 0; mi < 2; mi++) {
                int row  = wm * 32 + mi * 16 + r8 + ((sel & 1) << 3);
                int colh = kb + ((sel >> 1) << 3);
                uint32_t addr = asBase + (((buf * T2M + row) * TP + colh) << 1);
                ldsm_x4(af[mi][0], af[mi][1], af[mi][2], af[mi][3], addr);
            }
            #pragma unroll
            for (int nj = 0; nj < 2; nj++) {
                int row  = wn * 32 + nj * 16 + r8 + ((sel >> 1) << 3);
                int colh = kb + ((sel & 1) << 3);
                uint32_t addr = bsBase + (((buf * T2N + row) * TP + colh) << 1);
                ldsm_x4(bf[nj*2][0], bf[nj*2][1], bf[nj*2+1][0], bf[nj*2+1][1], addr);
            }
            #pragma unroll
            for (int mi = 0; mi < 2; mi++)
                #pragma unroll
                for (int ni = 0; ni < 4; ni++)
                    mma_f16(acc[mi][ni], af[mi][0], af[mi][1], af[mi][2], af[mi][3],
                            bf[ni][0], bf[ni][1]);
        }
    }

    const int lr = lane >> 2;
    const int lc = (lane & 3) * 2;
    #pragma unroll
    for (int mi = 0; mi < 2; mi++) {
        int r0 = bm + wm * 32 + mi * 16 + lr;
        #pragma unroll
        for (int ni = 0; ni < 4; ni++) {
            int c0 = bn + wn * 32 + ni * 8 + lc;
            float v0 = acc[mi][ni][0], v1 = acc[mi][ni][1];
            float v2 = acc[mi][ni][2], v3 = acc[mi][ni][3];
            if (bias) {
                float b0 = bias[c0], b1 = bias[c0 + 1];
                v0 += b0; v1 += b1; v2 += b0; v3 += b1;
            }
            if (res) {
                v0 += res[(size_t)r0 * N + c0];
                v1 += res[(size_t)r0 * N + c0 + 1];
                v2 += res[(size_t)(r0 + 8) * N + c0];
                v3 += res[(size_t)(r0 + 8) * N + c0 + 1];
            }
            if (doRelu) {
                v0 = fmaxf(v0, 0.f); v1 = fmaxf(v1, 0.f);
                v2 = fmaxf(v2, 0.f); v3 = fmaxf(v3, 0.f);
            }
            if (outMode == 0) {
                float* C = (float*)Cv;
                *(float2*)&C[(size_t)r0 * N + c0]       = make_float2(v0, v1);
                *(float2*)&C[(size_t)(r0 + 8) * N + c0] = make_float2(v2, v3);
            } else {
                __half* C = (__half*)Cv;
                *(__half2*)&C[(size_t)r0 * N + c0]       = __floats2half2_rn(v0, v1);
                *(__half2*)&C[(size_t)(r0 + 8) * N + c0] = __floats2half2_rn(v2, v3);
            }
        }
    }
}

// ============ tgemm128: proven 128x128 TBK=32 kernel (logits) ================
#define TBM 128
#define TBN 128
#define TBK 32

__global__ __launch_bounds__(256) void tgemm_kernel(
    const __half* __restrict__ A, const __half* __restrict__ W,
    const float* __restrict__ bias, const float* __restrict__ res,
    void* __restrict__ Cv, int M, int N, int K, int doRelu, int outMode)
{
    __shared__ __align__(16) __half As[2][TBM][TP];
    __shared__ __align__(16) __half Bs[2][TBN][TP];

    const int tid  = threadIdx.x;
    const int lane = tid & 31;
    const int warp = tid >> 5;
    const int wm   = warp >> 2;
    const int wn   = warp & 3;
    const int bm   = blockIdx.y * TBM;
    const int bn   = blockIdx.x * TBN;

    const uint32_t asBase = (uint32_t)__cvta_generic_to_shared(&As[0][0][0]);
    const uint32_t bsBase = (uint32_t)__cvta_generic_to_shared(&Bs[0][0][0]);

    float acc[4][4][4];
    #pragma unroll
    for (int i = 0; i < 4; i++)
        #pragma unroll
        for (int j = 0; j < 4; j++)
            #pragma unroll
            for (int t = 0; t < 4; t++) acc[i][j][t] = 0.f;

    const int KT = K / TBK;

    #pragma unroll
    for (int p = 0; p < 2; p++) {
        int c = tid + p * 256;
        int r = c >> 2, hoff = (c & 3) * 8;
        cp16(&As[0][r][hoff], A + (size_t)(bm + r) * K + hoff, 16);
        int gn = bn + r;
        int ok = (gn < N) ? 16 : 0;
        int gc = (gn < N) ? gn : (N - 1);
        cp16(&Bs[0][r][hoff], W + (size_t)gc * K + hoff, ok);
    }
    asm volatile("cp.async.commit_group;\n");

    const int r8  = lane & 7;
    const int sel = lane >> 3;

    for (int t = 0; t < KT; t++) {
        asm volatile("cp.async.wait_group 0;\n");
        __syncthreads();

        if (t + 1 < KT) {
            int nb = (t + 1) & 1;
            int k0 = (t + 1) * TBK;
            #pragma unroll
            for (int p = 0; p < 2; p++) {
                int c = tid + p * 256;
                int r = c >> 2, hoff = (c & 3) * 8;
                cp16(&As[nb][r][hoff], A + (size_t)(bm + r) * K + k0 + hoff, 16);
                int gn = bn + r;
                int ok = (gn < N) ? 16 : 0;
                int gc = (gn < N) ? gn : (N - 1);
                cp16(&Bs[nb][r][hoff], W + (size_t)gc * K + k0 + hoff, ok);
            }
            asm volatile("cp.async.commit_group;\n");
        }

        const int buf = t & 1;
        #pragma unroll
        for (int ks = 0; ks < 2; ks++) {
            const int kb = ks * 16;
            uint32_t af[4][4], bf[4][2];
            #pragma unroll
            for (int mi = 0; mi < 4; mi++) {
                int row  = wm * 64 + mi * 16 + r8 + ((sel & 1) << 3);
                int colh = kb + ((sel >> 1) << 3);
                uint32_t addr = asBase + (((buf * TBM + row) * TP + colh) << 1);
                ldsm_x4(af[mi][0], af[mi][1], af[mi][2], af[mi][3], addr);
            }
            #pragma unroll
            for (int nj = 0; nj < 2; nj++) {
                int row  = wn * 32 + nj * 16 + r8 + ((sel >> 1) << 3);
                int colh = kb + ((sel & 1) << 3);
                uint32_t addr = bsBase + (((buf * TBN + row) * TP + colh) << 1);
                ldsm_x4(bf[nj*2][0], bf[nj*2][1], bf[nj*2+1][0], bf[nj*2+1][1], addr);
            }
            #pragma unroll
            for (int mi = 0; mi < 4; mi++)
                #pragma unroll
                for (int ni = 0; ni < 4; ni++)
                    mma_f16(acc[mi][ni], af[mi][0], af[mi][1], af[mi][2], af[mi][3],
                            bf[ni][0], bf[ni][1]);
        }
        __syncthreads();
    }

    const int lr = lane >> 2;
    const int lc = (lane & 3) * 2;
    #pragma unroll
    for (int mi = 0; mi < 4; mi++) {
        int r0 = bm + wm * 64 + mi * 16 + lr;
        #pragma unroll
        for (int ni = 0; ni < 4; ni++) {
            int c0 = bn + wn * 32 + ni * 8 + lc;
            if (c0 >= N) continue;
            float v0 = acc[mi][ni][0], v1 = acc[mi][ni][1];
            float v2 = acc[mi][ni][2], v3 = acc[mi][ni][3];
            if (bias) {
                float b0 = bias[c0], b1 = bias[c0 + 1];
                v0 += b0; v1 += b1; v2 += b0; v3 += b1;
            }
            if (res) {
                v0 += res[(size_t)r0 * N + c0];
                v1 += res[(size_t)r0 * N + c0 + 1];
                v2 += res[(size_t)(r0 + 8) * N + c0];
                v3 += res[(size_t)(r0 + 8) * N + c0 + 1];
            }
            if (doRelu) {
                v0 = fmaxf(v0, 0.f); v1 = fmaxf(v1, 0.f);
                v2 = fmaxf(v2, 0.f); v3 = fmaxf(v3, 0.f);
            }
            if (outMode == 0) {
                float* C = (float*)Cv;
                *(float2*)&C[(size_t)r0 * N + c0]       = make_float2(v0, v1);
                *(float2*)&C[(size_t)(r0 + 8) * N + c0] = make_float2(v2, v3);
            } else {
                __half* C = (__half*)Cv;
                *(__half2*)&C[(size_t)r0 * N + c0]       = __floats2half2_rn(v0, v1);
                *(__half2*)&C[(size_t)(r0 + 8) * N + c0] = __floats2half2_rn(v2, v3);
            }
        }
    }
}

// ---------------- fp16 flash attention: 128q x 64k, P in registers ------------
#define APH 72
#define FATTN_SMEM ((128 + 128 + 128) * APH * 2)   // Q + 2xK + 2xV (no Ps)

extern __shared__ __half attn_smem[];

__global__ __launch_bounds__(256) void fattn_tc(
    const __half* __restrict__ Q, const __half* __restrict__ Kb,
    const __half* __restrict__ Vb, __half* __restrict__ O)
{
    __half* Qs = attn_smem;               // [128][APH]
    __half* Ks = Qs + 128 * APH;          // 2 x [64][APH]
    __half* Vk = Ks + 2 * 64 * APH;       // 2 x [64][APH]

    const int qt = (gridDim.x - 1) - blockIdx.x;
    const int h  = blockIdx.y, b = blockIdx.z;
    const int q0 = qt * 128;
    const int tid  = threadIdx.x;
    const int lane = tid & 31;
    const int warp = tid >> 5;            // 0..7

    const int OST = Hc * DHc;

    const int r0  = warp * 16 + (lane >> 2);
    const int kh  = (lane & 3) * 2;
    const int ls4 = lane >> 2;
    const int wrmax = warp * 16 + 15;     // max q-row (block-local) of this warp

    // load Q tile
    #pragma unroll
    for (int p = 0; p < 4; p++) {
        int c = tid + p * 256;
        int r = c >> 3, d8 = (c & 7) * 8;
        float4 v = *(const float4*)(Q + (size_t)(b * Sc + q0 + r) * QKVSTR + h * DHc + d8);
        *(float4*)&Qs[r * APH + d8] = v;
    }

    float o_acc[8][4];
    #pragma unroll
    for (int n = 0; n < 8; n++)
        #pragma unroll
        for (int t = 0; t < 4; t++) o_acc[n][t] = 0.f;
    float m0 = -1e30f, m1 = -1e30f, l0 = 0.f, l1 = 0.f;

    const int nt = 2 * qt + 2;
    const size_t kvrow0 = (size_t)(b * Sc) * QKVSTR + h * DHc;

    #pragma unroll
    for (int p = 0; p < 2; p++) {
        int c = tid + p * 256;
        int r = c >> 3, d8 = (c & 7) * 8;
        cp16(&Ks[r * APH + d8], Kb + kvrow0 + (size_t)r * QKVSTR + d8, 16);
        cp16(&Vk[r * APH + d8], Vb + kvrow0 + (size_t)r * QKVSTR + d8, 16);
    }
    asm volatile("cp.async.commit_group;\n");

    for (int kt = 0; kt < nt; kt++) {
        asm volatile("cp.async.wait_group 0;\n");
        __syncthreads();

        const int buf = kt & 1;
        if (kt + 1 < nt) {
            const int nb = buf ^ 1;
            const size_t base = kvrow0 + (size_t)(kt + 1) * 64 * QKVSTR;
            #pragma unroll
            for (int p = 0; p < 2; p++) {
                int c = tid + p * 256;
                int r = c >> 3, d8 = (c & 7) * 8;
                cp16(&Ks[nb * 64 * APH + r * APH + d8], Kb + base + (size_t)r * QKVSTR + d8, 16);
                cp16(&Vk[nb * 64 * APH + r * APH + d8], Vb + base + (size_t)r * QKVSTR + d8, 16);
            }
        }
        asm volatile("cp.async.commit_group;\n");

        // warp-level skip: tile fully masked for this warp's rows?
        const int koff = kt * 64 - 128 * qt;
        if (koff > wrmax) continue;       // warp-uniform; syncs already done

        const __half* Kt = Ks + buf * 64 * APH;
        const __half* Vt = Vk + buf * 64 * APH;

        float sacc[8][4];
        #pragma unroll
        for (int n = 0; n < 8; n++)
            #pragma unroll
            for (int t = 0; t < 4; t++) sacc[n][t] = 0.f;

        #pragma unroll
        for (int ks = 0; ks < 4; ks++) {
            const int kb = ks * 16;
            uint32_t a0 = *(const uint32_t*)&Qs[ r0      * APH + kb + kh];
            uint32_t a1 = *(const uint32_t*)&Qs[(r0 + 8) * APH + kb + kh];
            uint32_t a2 = *(const uint32_t*)&Qs[ r0      * APH + kb + kh + 8];
            uint32_t a3 = *(const uint32_t*)&Qs[(r0 + 8) * APH + kb + kh + 8];
            #pragma unroll
            for (int n = 0; n < 8; n++) {
                const int nr = n * 8 + ls4;
                uint32_t b0 = *(const uint32_t*)&Kt[nr * APH + kb + kh];
                uint32_t b1 = *(const uint32_t*)&Kt[nr * APH + kb + kh + 8];
                mma_f16(sacc[n], a0, a1, a2, a3, b0, b1);
            }
        }

        if (koff > -64) {
            #pragma unroll
            for (int n = 0; n < 8; n++) {
                const int c0 = koff + n * 8 + (lane & 3) * 2;
                if (c0     > r0)     sacc[n][0] = -1e30f;
                if (c0 + 1 > r0)     sacc[n][1] = -1e30f;
                if (c0     > r0 + 8) sacc[n][2] = -1e30f;
                if (c0 + 1 > r0 + 8) sacc[n][3] = -1e30f;
            }
        }

        float mx0 = -1e30f, mx1 = -1e30f;
        #pragma unroll
        for (int n = 0; n < 8; n++) {
            mx0 = fmaxf(mx0, fmaxf(sacc[n][0], sacc[n][1]));
            mx1 = fmaxf(mx1, fmaxf(sacc[n][2], sacc[n][3]));
        }
        mx0 = fmaxf(mx0, __shfl_xor_sync(0xffffffffu, mx0, 1));
        mx0 = fmaxf(mx0, __shfl_xor_sync(0xffffffffu, mx0, 2));
        mx1 = fmaxf(mx1, __shfl_xor_sync(0xffffffffu, mx1, 1));
        mx1 = fmaxf(mx1, __shfl_xor_sync(0xffffffffu, mx1, 2));

        const float mn0 = fmaxf(m0, mx0);
        const float mn1 = fmaxf(m1, mx1);
        const float cr0 = __expf(m0 - mn0);
        const float cr1 = __expf(m1 - mn1);
        float s0 = 0.f, s1 = 0.f;
        #pragma unroll
        for (int n = 0; n < 8; n++) {
            float p00 = __expf(sacc[n][0] - mn0);
            float p01 = __expf(sacc[n][1] - mn0);
            float p10 = __expf(sacc[n][2] - mn1);
            float p11 = __expf(sacc[n][3] - mn1);
            s0 += p00 + p01;
            s1 += p10 + p11;
            sacc[n][0] = p00; sacc[n][1] = p01;
            sacc[n][2] = p10; sacc[n][3] = p11;
        }
        s0 += __shfl_xor_sync(0xffffffffu, s0, 1);
        s0 += __shfl_xor_sync(0xffffffffu, s0, 2);
        s1 += __shfl_xor_sync(0xffffffffu, s1, 1);
        s1 += __shfl_xor_sync(0xffffffffu, s1, 2);

        l0 = l0 * cr0 + s0;  m0 = mn0;
        l1 = l1 * cr1 + s1;  m1 = mn1;
        #pragma unroll
        for (int n = 0; n < 8; n++) {
            o_acc[n][0] *= cr0; o_acc[n][1] *= cr0;
            o_acc[n][2] *= cr1; o_acc[n][3] *= cr1;
        }

        // O += P @ V : A-fragments packed directly from softmax registers.
        // A frag (k chunk kb=16j): a0/a1 cols kb+(lane&3)*2 (+row 8) = sacc[2j] c0..c3,
        //                          a2/a3 cols +8            = sacc[2j+1] c0..c3.
        #pragma unroll
        for (int j = 0; j < 4; j++) {
            const int kb = j * 16;
            uint32_t a0 = f2h2(sacc[2*j][0],   sacc[2*j][1]);
            uint32_t a1 = f2h2(sacc[2*j][2],   sacc[2*j][3]);
            uint32_t a2 = f2h2(sacc[2*j+1][0], sacc[2*j+1][1]);
            uint32_t a3 = f2h2(sacc[2*j+1][2], sacc[2*j+1][3]);
            uint32_t base = (uint32_t)__cvta_generic_to_shared(
                                &Vt[(kb + (lane & 15)) * APH]);
            #pragma unroll
            for (int n = 0; n < 8; n++) {
                uint32_t b0, b1;
                ldsm_x2_trans(b0, b1, base + n * 16);
                mma_f16(o_acc[n], a0, a1, a2, a3, b0, b1);
            }
        }
    }

    const float inv0 = 1.f / l0;
    const float inv1 = 1.f / l1;
    #pragma unroll
    for (int n = 0; n < 8; n++) {
        const int c0 = n * 8 + (lane & 3) * 2;
        size_t o0 = (size_t)(b * Sc + q0 + r0)     * OST + h * DHc + c0;
        size_t o1 = (size_t)(b * Sc + q0 + r0 + 8) * OST + h * DHc + c0;
        *(__half2*)&O[o0] = __floats2half2_rn(o_acc[n][0] * inv0, o_acc[n][1] * inv0);
        *(__half2*)&O[o1] = __floats2half2_rn(o_acc[n][2] * inv1, o_acc[n][3] * inv1);
    }
}

// ---------------- LayerNorm over D=512 (single-pass reduction) ----------------
__global__ void ln_kernel(const float* __restrict__ X, const float* __restrict__ g,
                          const float* __restrict__ bta, float* __restrict__ Y,
                          __half* __restrict__ Yt) {
    int row = blockIdx.x;
    const float* x = X + (size_t)row * Dc;
    float*  y  = Y  + (size_t)row * Dc;
    __half* yt = Yt + (size_t)row * Dc;
    int tid = threadIdx.x;
    int d0  = tid * 4;

    float4 v = *(const float4*)(x + d0);
    float sum = v.x + v.y + v.z + v.w;
    float sq  = v.x*v.x + v.y*v.y + v.z*v.z + v.w*v.w;

    __shared__ float redS[4], redQ[4];
    #pragma unroll
    for (int off = 16; off; off >>= 1) {
        sum += __shfl_xor_sync(0xffffffffu, sum, off);
        sq  += __shfl_xor_sync(0xffffffffu, sq,  off);
    }
    if ((tid & 31) == 0) { redS[tid >> 5] = sum; redQ[tid >> 5] = sq; }
    __syncthreads();
    sum = redS[0] + redS[1] + redS[2] + redS[3];
    sq  = redQ[0] + redQ[1] + redQ[2] + redQ[3];
    float mean = sum * (1.f / Dc);
    float var  = sq * (1.f / Dc) - mean * mean;
    float rstd = rsqrtf(var + 1e-5f);

    float4 gg = *(const float4*)(g + d0);
    float4 bb = *(const float4*)(bta + d0);
    float4 o;
    o.x = (v.x - mean) * rstd * gg.x + bb.x;
    o.y = (v.y - mean) * rstd * gg.y + bb.y;
    o.z = (v.z - mean) * rstd * gg.z + bb.z;
    o.w = (v.w - mean) * rstd * gg.w + bb.w;
    *(float4*)(y + d0) = o;
    __half2 ho[2];
    ho[0] = __floats2half2_rn(o.x, o.y);
    ho[1] = __floats2half2_rn(o.z, o.w);
    *(uint2*)(yt + d0) = *(uint2*)ho;
}

// ---------------- launch ----------------------------------------------------
extern "C" void kernel_launch(void* const* d_in, const int* in_sizes, int n_in,
                              void* d_out, int out_size) {
    const int*   data = (const int*)  d_in[0];
    const float* we   = (const float*)d_in[1];
    const float* pe   = (const float*)d_in[2];
    const float* Wq   = (const float*)d_in[3];
    const float* Wkv  = (const float*)d_in[4];
    const float* Wo   = (const float*)d_in[5];
    const float* g1   = (const float*)d_in[6];
    const float* bl1  = (const float*)d_in[7];
    const float* W1   = (const float*)d_in[8];
    const float* bf1  = (const float*)d_in[9];
    const float* W2   = (const float*)d_in[10];
    const float* bf2  = (const float*)d_in[11];
    const float* g2   = (const float*)d_in[12];
    const float* bl2  = (const float*)d_in[13];
    const float* outb = (const float*)d_in[14];
    float* out = (float*)d_out;

    float *h, *tmp;
    __half *ht, *qkv, *aot, *fft;
    __half *wqkv, *wo_t, *w1_t, *w2_t, *we_t;
    cudaGetSymbolAddress((void**)&h,    g_h);
    cudaGetSymbolAddress((void**)&ht,   g_ht);
    cudaGetSymbolAddress((void**)&qkv,  g_qkv);
    cudaGetSymbolAddress((void**)&aot,  g_aot);
    cudaGetSymbolAddress((void**)&tmp,  g_tmp);
    cudaGetSymbolAddress((void**)&fft,  g_fft);
    cudaGetSymbolAddress((void**)&wqkv, g_wqkv);
    cudaGetSymbolAddress((void**)&wo_t, g_wo_t);
    cudaGetSymbolAddress((void**)&w1_t, g_w1_t);
    cudaGetSymbolAddress((void**)&w2_t, g_w2_t);
    cudaGetSymbolAddress((void**)&we_t, g_we_t);

    cudaFuncSetAttribute(fattn_tc, cudaFuncAttributeMaxDynamicSharedMemorySize, FATTN_SMEM);

    {
        int n8;
        n8 = Lc * QKVSTR * Dc / 8;  pack_qkv_w8<<<(n8 + 255)/256, 256>>>(Wq, Wkv, wqkv);
        n8 = Lc * Dc * Dc / 8;      cvt_w8<<<(n8 + 255)/256, 256>>>(Wo, wo_t, n8);
        n8 = Lc * DIc * Dc / 8;     cvt_w8<<<(n8 + 255)/256, 256>>>(W1, w1_t, n8);
        n8 = Lc * Dc * DIc / 8;     cvt_w8<<<(n8 + 255)/256, 256>>>(W2, w2_t, n8);
        n8 = Vc * Dc / 8;           cvt_w8<<<(n8 + 255)/256, 256>>>(we, we_t, n8);
    }

    embed_kernel<<<(M_ROWS*Dc/4 + 255)/256, 256>>>(data, we, pe, h, ht);

    dim3 g64D  ( Dc/128,     M_ROWS/64);
    dim3 g64QKV( QKVSTR/128, M_ROWS/64);
    dim3 g64DI ( DIc/128,    M_ROWS/64);
    dim3 gsV   ((Vc + 127)/128, M_ROWS/128);
    dim3 gsA   (Sc/128, Hc, Bc);

    for (int l = 0; l < Lc; l++) {
        tgemm64_kernel<<<g64QKV, 256>>>(ht, wqkv + (size_t)l*QKVSTR*Dc, nullptr, nullptr,
                                        qkv, M_ROWS, QKVSTR, Dc, 0, 1);

        fattn_tc<<<gsA, 256, FATTN_SMEM>>>(qkv, qkv + Dc, qkv + 2*Dc, aot);

        tgemm64_kernel<<<g64D, 256>>>(aot, wo_t + (size_t)l*Dc*Dc, nullptr, h, tmp,
                                      M_ROWS, Dc, Dc, 0, 0);
        ln_kernel<<<M_ROWS, 128>>>(tmp, g1 + (size_t)l*Dc, bl1 + (size_t)l*Dc, h, ht);

        tgemm64_kernel<<<g64DI, 256>>>(ht, w1_t + (size_t)l*DIc*Dc, bf1 + (size_t)l*DIc, nullptr,
                                       fft, M_ROWS, DIc, Dc, 1, 1);
        tgemm64_kernel<<<g64D, 256>>>(fft, w2_t + (size_t)l*Dc*DIc, bf2 + (size_t)l*Dc, h,
                                      tmp, M_ROWS, Dc, DIc, 0, 0);
        ln_kernel<<<M_ROWS, 128>>>(tmp, g2 + (size_t)l*Dc, bl2 + (size_t)l*Dc, h, ht);
    }

    tgemm_kernel<<<gsV, 256>>>(ht, we_t, outb, nullptr, out, M_ROWS, Vc, Dc, 0, 0);
}

// round 14
// speedup vs baseline: 1.1015x; 1.0782x over previous
#include <cuda_runtime.h>
#include <cuda_fp16.h>
#include <math.h>
#include <stdint.h>

#define Bc 4
#define Sc 1024
#define Dc 512
#define Hc 8
#define DHc 64
#define DIc 2048
#define Lc 12
#define Vc 10000
#define M_ROWS (Bc*Sc)   /* 4096 */
#define QKVSTR (3*Dc)    /* 1536 */

// ---------------- scratch (no allocations allowed) ----------------
__device__ float  g_h   [M_ROWS*Dc];
__device__ __half g_ht  [M_ROWS*Dc];
__device__ __half g_qkv [M_ROWS*QKVSTR];
__device__ __half g_aot [M_ROWS*Dc];
__device__ float  g_tmp [M_ROWS*Dc];
__device__ __half g_fft [M_ROWS*DIc];
__device__ __half g_wqkv[Lc*QKVSTR*Dc];
__device__ __half g_wo_t[Lc*Dc*Dc];
__device__ __half g_w1_t[Lc*DIc*Dc];
__device__ __half g_w2_t[Lc*Dc*DIc];
__device__ __half g_we_t[Vc*Dc];

// ---------------- helpers ----------------------------------------------------
__device__ __forceinline__ void cp16(void* smem, const void* g, int srcBytes) {
    uint32_t s = (uint32_t)__cvta_generic_to_shared(smem);
    asm volatile("cp.async.cg.shared.global [%0], [%1], 16, %2;\n"
                 :: "r"(s), "l"(g), "r"(srcBytes));
}

__device__ __forceinline__ void mma_f16(float c[4],
    uint32_t a0, uint32_t a1, uint32_t a2, uint32_t a3,
    uint32_t b0, uint32_t b1)
{
    asm volatile(
        "mma.sync.aligned.m16n8k16.row.col.f32.f16.f16.f32 "
        "{%0,%1,%2,%3}, {%4,%5,%6,%7}, {%8,%9}, {%0,%1,%2,%3};"
        : "+f"(c[0]), "+f"(c[1]), "+f"(c[2]), "+f"(c[3])
        : "r"(a0), "r"(a1), "r"(a2), "r"(a3), "r"(b0), "r"(b1));
}

__device__ __forceinline__ void ldsm_x4(uint32_t& r0, uint32_t& r1,
                                        uint32_t& r2, uint32_t& r3, uint32_t addr) {
    asm volatile("ldmatrix.sync.aligned.m8n8.x4.shared.b16 {%0,%1,%2,%3}, [%4];"
                 : "=r"(r0), "=r"(r1), "=r"(r2), "=r"(r3) : "r"(addr));
}

__device__ __forceinline__ void ldsm_x2_trans(uint32_t& r0, uint32_t& r1, uint32_t addr) {
    asm volatile("ldmatrix.sync.aligned.m8n8.x2.trans.shared.b16 {%0,%1}, [%2];"
                 : "=r"(r0), "=r"(r1) : "r"(addr));
}

__device__ __forceinline__ uint32_t f2h2(float a, float b) {
    __half2 h = __floats2half2_rn(a, b);
    return *(uint32_t*)&h;
}

// ---------------- weight preconversion (vectorized) ---------------------------
__global__ void pack_qkv_w8(const float* __restrict__ Wq, const float* __restrict__ Wkv,
                            __half* __restrict__ dst) {
    int i = blockIdx.x * blockDim.x + threadIdx.x;
    const int NC8 = Dc / 8;
    if (i >= Lc * QKVSTR * NC8) return;
    int c8 = (i % NC8) * 8;
    int r  = (i / NC8) % QKVSTR;
    int l  = i / (NC8 * QKVSTR);
    const float* src;
    float sc;
    if (r < Dc) { src = Wq  + ((size_t)l * Dc + r) * Dc + c8;              sc = 0.125f; }
    else        { src = Wkv + ((size_t)l * 2 * Dc + (r - Dc)) * Dc + c8;   sc = 1.f; }
    float4 x = *(const float4*)src;
    float4 y = *(const float4*)(src + 4);
    __half2 o[4];
    o[0] = __floats2half2_rn(x.x * sc, x.y * sc);
    o[1] = __floats2half2_rn(x.z * sc, x.w * sc);
    o[2] = __floats2half2_rn(y.x * sc, y.y * sc);
    o[3] = __floats2half2_rn(y.z * sc, y.w * sc);
    *(uint4*)&dst[(size_t)i * 8] = *(uint4*)o;
}

__global__ void cvt_w8(const float* __restrict__ src, __half* __restrict__ dst, int n8) {
    int i = blockIdx.x * blockDim.x + threadIdx.x;
    if (i >= n8) return;
    float4 x = *(const float4*)(src + (size_t)i * 8);
    float4 y = *(const float4*)(src + (size_t)i * 8 + 4);
    __half2 o[4];
    o[0] = __floats2half2_rn(x.x, x.y);
    o[1] = __floats2half2_rn(x.z, x.w);
    o[2] = __floats2half2_rn(y.x, y.y);
    o[3] = __floats2half2_rn(y.z, y.w);
    *(uint4*)&dst[(size_t)i * 8] = *(uint4*)o;
}

// ---------------- embedding (4 elems/thread) ----------------
__global__ void embed_kernel(const int* __restrict__ data,
                             const float* __restrict__ we,
                             const float* __restrict__ pe,
                             float* __restrict__ h, __half* __restrict__ ht) {
    int i = blockIdx.x * blockDim.x + threadIdx.x;
    if (i >= M_ROWS * Dc / 4) return;
    int d4  = (i % (Dc / 4)) * 4;
    int row = i / (Dc / 4);
    int s   = row % Sc;
    int tok = data[row];
    float4 a = *(const float4*)(we + (size_t)tok * Dc + d4);
    float4 p = *(const float4*)(pe + (size_t)s   * Dc + d4);
    float4 v = make_float4(a.x + p.x, a.y + p.y, a.z + p.z, a.w + p.w);
    *(float4*)&h[(size_t)row * Dc + d4] = v;
    __half2 o[2];
    o[0] = __floats2half2_rn(v.x, v.y);
    o[1] = __floats2half2_rn(v.z, v.w);
    *(uint2*)&ht[(size_t)row * Dc + d4] = *(uint2*)o;
}

// ============ tgemm64: TBM=64, TBN=128, 3-stage pipeline, 1 sync/iter =========
#define T2M 64
#define T2N 128
#define T2K 32
#define TP 40

__global__ __launch_bounds__(256) void tgemm64_kernel(
    const __half* __restrict__ A, const __half* __restrict__ W,
    const float* __restrict__ bias, const float* __restrict__ res,
    void* __restrict__ Cv, int M, int N, int K, int doRelu, int outMode)
{
    __shared__ __align__(16) __half As[3][T2M][TP];
    __shared__ __align__(16) __half Bs[3][T2N][TP];

    const int tid  = threadIdx.x;
    const int lane = tid & 31;
    const int warp = tid >> 5;
    const int wm   = warp >> 2;
    const int wn   = warp & 3;
    const int bm   = blockIdx.y * T2M;
    const int bn   = blockIdx.x * T2N;

    const uint32_t asBase = (uint32_t)__cvta_generic_to_shared(&As[0][0][0]);
    const uint32_t bsBase = (uint32_t)__cvta_generic_to_shared(&Bs[0][0][0]);

    float acc[2][4][4];
    #pragma unroll
    for (int i = 0; i < 2; i++)
        #pragma unroll
        for (int j = 0; j < 4; j++)
            #pragma unroll
            for (int t = 0; t < 4; t++) acc[i][j][t] = 0.f;

    const int KT = K / T2K;
    const int rA  = tid >> 2, hA = (tid & 3) * 8;

    #pragma unroll
    for (int s = 0; s < 2; s++) {
        int k0 = s * T2K;
        cp16(&As[s][rA][hA], A + (size_t)(bm + rA) * K + k0 + hA, 16);
        #pragma unroll
        for (int p = 0; p < 2; p++) {
            int c = tid + p * 256;
            int r = c >> 2, hf = (c & 3) * 8;
            cp16(&Bs[s][r][hf], W + (size_t)(bn + r) * K + k0 + hf, 16);
        }
        asm volatile("cp.async.commit_group;\n");
    }

    const int r8  = lane & 7;
    const int sel = lane >> 3;

    for (int t = 0; t < KT; t++) {
        asm volatile("cp.async.wait_group 1;\n");
        __syncthreads();

        {
            int tp = t + 2;
            if (tp < KT) {
                int sb = tp % 3;
                int k0 = tp * T2K;
                cp16(&As[sb][rA][hA], A + (size_t)(bm + rA) * K + k0 + hA, 16);
                #pragma unroll
                for (int p = 0; p < 2; p++) {
                    int c = tid + p * 256;
                    int r = c >> 2, hf = (c & 3) * 8;
                    cp16(&Bs[sb][r][hf], W + (size_t)(bn + r) * K + k0 + hf, 16);
                }
            }
            asm volatile("cp.async.commit_group;\n");
        }

        const int buf = t % 3;
        #pragma unroll
        for (int ks = 0; ks < 2; ks++) {
            const int kb = ks * 16;
            uint32_t af[2][4], bf[4][2];
            #pragma unroll
            for (int mi = 0; mi < 2; mi++) {
                int row  = wm * 32 + mi * 16 + r8 + ((sel & 1) << 3);
                int colh = kb + ((sel >> 1) << 3);
                uint32_t addr = asBase + (((buf * T2M + row) * TP + colh) << 1);
                ldsm_x4(af[mi][0], af[mi][1], af[mi][2], af[mi][3], addr);
            }
            #pragma unroll
            for (int nj = 0; nj < 2; nj++) {
                int row  = wn * 32 + nj * 16 + r8 + ((sel >> 1) << 3);
                int colh = kb + ((sel & 1) << 3);
                uint32_t addr = bsBase + (((buf * T2N + row) * TP + colh) << 1);
                ldsm_x4(bf[nj*2][0], bf[nj*2][1], bf[nj*2+1][0], bf[nj*2+1][1], addr);
            }
            #pragma unroll
            for (int mi = 0; mi < 2; mi++)
                #pragma unroll
                for (int ni = 0; ni < 4; ni++)
                    mma_f16(acc[mi][ni], af[mi][0], af[mi][1], af[mi][2], af[mi][3],
                            bf[ni][0], bf[ni][1]);
        }
    }

    const int lr = lane >> 2;
    const int lc = (lane & 3) * 2;
    #pragma unroll
    for (int mi = 0; mi < 2; mi++) {
        int r0 = bm + wm * 32 + mi * 16 + lr;
        #pragma unroll
        for (int ni = 0; ni < 4; ni++) {
            int c0 = bn + wn * 32 + ni * 8 + lc;
            float v0 = acc[mi][ni][0], v1 = acc[mi][ni][1];
            float v2 = acc[mi][ni][2], v3 = acc[mi][ni][3];
            if (bias) {
                float b0 = bias[c0], b1 = bias[c0 + 1];
                v0 += b0; v1 += b1; v2 += b0; v3 += b1;
            }
            if (res) {
                v0 += res[(size_t)r0 * N + c0];
                v1 += res[(size_t)r0 * N + c0 + 1];
                v2 += res[(size_t)(r0 + 8) * N + c0];
                v3 += res[(size_t)(r0 + 8) * N + c0 + 1];
            }
            if (doRelu) {
                v0 = fmaxf(v0, 0.f); v1 = fmaxf(v1, 0.f);
                v2 = fmaxf(v2, 0.f); v3 = fmaxf(v3, 0.f);
            }
            if (outMode == 0) {
                float* C = (float*)Cv;
                *(float2*)&C[(size_t)r0 * N + c0]       = make_float2(v0, v1);
                *(float2*)&C[(size_t)(r0 + 8) * N + c0] = make_float2(v2, v3);
            } else {
                __half* C = (__half*)Cv;
                *(__half2*)&C[(size_t)r0 * N + c0]       = __floats2half2_rn(v0, v1);
                *(__half2*)&C[(size_t)(r0 + 8) * N + c0] = __floats2half2_rn(v2, v3);
            }
        }
    }
}

// ============ tgemm128: proven 128x128 TBK=32 kernel (logits) ================
#define TBM 128
#define TBN 128
#define TBK 32

__global__ __launch_bounds__(256) void tgemm_kernel(
    const __half* __restrict__ A, const __half* __restrict__ W,
    const float* __restrict__ bias, const float* __restrict__ res,
    void* __restrict__ Cv, int M, int N, int K, int doRelu, int outMode)
{
    __shared__ __align__(16) __half As[2][TBM][TP];
    __shared__ __align__(16) __half Bs[2][TBN][TP];

    const int tid  = threadIdx.x;
    const int lane = tid & 31;
    const int warp = tid >> 5;
    const int wm   = warp >> 2;
    const int wn   = warp & 3;
    const int bm   = blockIdx.y * TBM;
    const int bn   = blockIdx.x * TBN;

    const uint32_t asBase = (uint32_t)__cvta_generic_to_shared(&As[0][0][0]);
    const uint32_t bsBase = (uint32_t)__cvta_generic_to_shared(&Bs[0][0][0]);

    float acc[4][4][4];
    #pragma unroll
    for (int i = 0; i < 4; i++)
        #pragma unroll
        for (int j = 0; j < 4; j++)
            #pragma unroll
            for (int t = 0; t < 4; t++) acc[i][j][t] = 0.f;

    const int KT = K / TBK;

    #pragma unroll
    for (int p = 0; p < 2; p++) {
        int c = tid + p * 256;
        int r = c >> 2, hoff = (c & 3) * 8;
        cp16(&As[0][r][hoff], A + (size_t)(bm + r) * K + hoff, 16);
        int gn = bn + r;
        int ok = (gn < N) ? 16 : 0;
        int gc = (gn < N) ? gn : (N - 1);
        cp16(&Bs[0][r][hoff], W + (size_t)gc * K + hoff, ok);
    }
    asm volatile("cp.async.commit_group;\n");

    const int r8  = lane & 7;
    const int sel = lane >> 3;

    for (int t = 0; t < KT; t++) {
        asm volatile("cp.async.wait_group 0;\n");
        __syncthreads();

        if (t + 1 < KT) {
            int nb = (t + 1) & 1;
            int k0 = (t + 1) * TBK;
            #pragma unroll
            for (int p = 0; p < 2; p++) {
                int c = tid + p * 256;
                int r = c >> 2, hoff = (c & 3) * 8;
                cp16(&As[nb][r][hoff], A + (size_t)(bm + r) * K + k0 + hoff, 16);
                int gn = bn + r;
                int ok = (gn < N) ? 16 : 0;
                int gc = (gn < N) ? gn : (N - 1);
                cp16(&Bs[nb][r][hoff], W + (size_t)gc * K + k0 + hoff, ok);
            }
            asm volatile("cp.async.commit_group;\n");
        }

        const int buf = t & 1;
        #pragma unroll
        for (int ks = 0; ks < 2; ks++) {
            const int kb = ks * 16;
            uint32_t af[4][4], bf[4][2];
            #pragma unroll
            for (int mi = 0; mi < 4; mi++) {
                int row  = wm * 64 + mi * 16 + r8 + ((sel & 1) << 3);
                int colh = kb + ((sel >> 1) << 3);
                uint32_t addr = asBase + (((buf * TBM + row) * TP + colh) << 1);
                ldsm_x4(af[mi][0], af[mi][1], af[mi][2], af[mi][3], addr);
            }
            #pragma unroll
            for (int nj = 0; nj < 2; nj++) {
                int row  = wn * 32 + nj * 16 + r8 + ((sel >> 1) << 3);
                int colh = kb + ((sel & 1) << 3);
                uint32_t addr = bsBase + (((buf * TBN + row) * TP + colh) << 1);
                ldsm_x4(bf[nj*2][0], bf[nj*2][1], bf[nj*2+1][0], bf[nj*2+1][1], addr);
            }
            #pragma unroll
            for (int mi = 0; mi < 4; mi++)
                #pragma unroll
                for (int ni = 0; ni < 4; ni++)
                    mma_f16(acc[mi][ni], af[mi][0], af[mi][1], af[mi][2], af[mi][3],
                            bf[ni][0], bf[ni][1]);
        }
        __syncthreads();
    }

    const int lr = lane >> 2;
    const int lc = (lane & 3) * 2;
    #pragma unroll
    for (int mi = 0; mi < 4; mi++) {
        int r0 = bm + wm * 64 + mi * 16 + lr;
        #pragma unroll
        for (int ni = 0; ni < 4; ni++) {
            int c0 = bn + wn * 32 + ni * 8 + lc;
            if (c0 >= N) continue;
            float v0 = acc[mi][ni][0], v1 = acc[mi][ni][1];
            float v2 = acc[mi][ni][2], v3 = acc[mi][ni][3];
            if (bias) {
                float b0 = bias[c0], b1 = bias[c0 + 1];
                v0 += b0; v1 += b1; v2 += b0; v3 += b1;
            }
            if (res) {
                v0 += res[(size_t)r0 * N + c0];
                v1 += res[(size_t)r0 * N + c0 + 1];
                v2 += res[(size_t)(r0 + 8) * N + c0];
                v3 += res[(size_t)(r0 + 8) * N + c0 + 1];
            }
            if (doRelu) {
                v0 = fmaxf(v0, 0.f); v1 = fmaxf(v1, 0.f);
                v2 = fmaxf(v2, 0.f); v3 = fmaxf(v3, 0.f);
            }
            if (outMode == 0) {
                float* C = (float*)Cv;
                *(float2*)&C[(size_t)r0 * N + c0]       = make_float2(v0, v1);
                *(float2*)&C[(size_t)(r0 + 8) * N + c0] = make_float2(v2, v3);
            } else {
                __half* C = (__half*)Cv;
                *(__half2*)&C[(size_t)r0 * N + c0]       = __floats2half2_rn(v0, v1);
                *(__half2*)&C[(size_t)(r0 + 8) * N + c0] = __floats2half2_rn(v2, v3);
            }
        }
    }
}

// ---------------- fp16 flash attention: balanced q-tile pairs -----------------
// 64q x 64k tiles, 4 warps, P in registers. Block handles q-tiles {i, 15-i}
// => every block does exactly 17 kv-tiles (perfect balance in one wave).
#define APH 72
#define NT64 (Sc/64)                       /* 16 q/kv tiles per (b,h) */
#define FATTN_SMEM ((64 + 128 + 128) * APH * 2)   // Q + 2xK + 2xV = 46KB

extern __shared__ __half attn_smem[];

__global__ __launch_bounds__(128) void fattn_tc(
    const __half* __restrict__ Q, const __half* __restrict__ Kb,
    const __half* __restrict__ Vb, __half* __restrict__ O)
{
    __half* Qs = attn_smem;               // [64][APH]
    __half* Ks = Qs + 64 * APH;           // 2 x [64][APH]
    __half* Vk = Ks + 2 * 64 * APH;       // 2 x [64][APH]

    const int qpair = blockIdx.x;         // 0..7
    const int h  = blockIdx.y, b = blockIdx.z;
    const int tid  = threadIdx.x;
    const int lane = tid & 31;
    const int warp = tid >> 5;            // 0..3

    const int OST = Hc * DHc;

    const int r0  = warp * 16 + (lane >> 2);
    const int kh  = (lane & 3) * 2;
    const int ls4 = lane >> 2;

    const size_t kvrow0 = (size_t)(b * Sc) * QKVSTR + h * DHc;

    #pragma unroll
    for (int seg = 0; seg < 2; seg++) {
        const int qt = seg ? (NT64 - 1 - qpair) : qpair;
        const int q0 = qt * 64;

        __syncthreads();   // prior segment's Qs reads complete before overwrite

        // load Q tile: 64 rows x 128B = 512 x 16B chunks over 128 threads
        #pragma unroll
        for (int p = 0; p < 4; p++) {
            int c = tid + p * 128;
            int r = c >> 3, d8 = (c & 7) * 8;
            float4 v = *(const float4*)(Q + (size_t)(b * Sc + q0 + r) * QKVSTR + h * DHc + d8);
            *(float4*)&Qs[r * APH + d8] = v;
        }

        float o_acc[8][4];
        #pragma unroll
        for (int n = 0; n < 8; n++)
            #pragma unroll
            for (int t = 0; t < 4; t++) o_acc[n][t] = 0.f;
        float m0 = -1e30f, m1 = -1e30f, l0 = 0.f, l1 = 0.f;

        const int nt = qt + 1;

        // prologue: kv tile 0
        #pragma unroll
        for (int p = 0; p < 4; p++) {
            int c = tid + p * 128;
            int r = c >> 3, d8 = (c & 7) * 8;
            cp16(&Ks[r * APH + d8], Kb + kvrow0 + (size_t)r * QKVSTR + d8, 16);
            cp16(&Vk[r * APH + d8], Vb + kvrow0 + (size_t)r * QKVSTR + d8, 16);
        }
        asm volatile("cp.async.commit_group;\n");

        for (int kt = 0; kt < nt; kt++) {
            asm volatile("cp.async.wait_group 0;\n");
            __syncthreads();

            const int buf = kt & 1;
            if (kt + 1 < nt) {
                const int nb = buf ^ 1;
                const size_t base = kvrow0 + (size_t)(kt + 1) * 64 * QKVSTR;
                #pragma unroll
                for (int p = 0; p < 4; p++) {
                    int c = tid + p * 128;
                    int r = c >> 3, d8 = (c & 7) * 8;
                    cp16(&Ks[nb * 64 * APH + r * APH + d8], Kb + base + (size_t)r * QKVSTR + d8, 16);
                    cp16(&Vk[nb * 64 * APH + r * APH + d8], Vb + base + (size_t)r * QKVSTR + d8, 16);
                }
            }
            asm volatile("cp.async.commit_group;\n");

            const __half* Kt = Ks + buf * 64 * APH;
            const __half* Vt = Vk + buf * 64 * APH;

            float sacc[8][4];
            #pragma unroll
            for (int n = 0; n < 8; n++)
                #pragma unroll
                for (int t = 0; t < 4; t++) sacc[n][t] = 0.f;

            #pragma unroll
            for (int ks = 0; ks < 4; ks++) {
                const int kb = ks * 16;
                uint32_t a0 = *(const uint32_t*)&Qs[ r0      * APH + kb + kh];
                uint32_t a1 = *(const uint32_t*)&Qs[(r0 + 8) * APH + kb + kh];
                uint32_t a2 = *(const uint32_t*)&Qs[ r0      * APH + kb + kh + 8];
                uint32_t a3 = *(const uint32_t*)&Qs[(r0 + 8) * APH + kb + kh + 8];
                #pragma unroll
                for (int n = 0; n < 8; n++) {
                    const int nr = n * 8 + ls4;
                    uint32_t b0 = *(const uint32_t*)&Kt[nr * APH + kb + kh];
                    uint32_t b1 = *(const uint32_t*)&Kt[nr * APH + kb + kh + 8];
                    mma_f16(sacc[n], a0, a1, a2, a3, b0, b1);
                }
            }

            if (kt == qt) {   // diagonal tile: causal mask
                #pragma unroll
                for (int n = 0; n < 8; n++) {
                    const int c0 = n * 8 + (lane & 3) * 2;
                    if (c0     > r0)     sacc[n][0] = -1e30f;
                    if (c0 + 1 > r0)     sacc[n][1] = -1e30f;
                    if (c0     > r0 + 8) sacc[n][2] = -1e30f;
                    if (c0 + 1 > r0 + 8) sacc[n][3] = -1e30f;
                }
            }

            float mx0 = -1e30f, mx1 = -1e30f;
            #pragma unroll
            for (int n = 0; n < 8; n++) {
                mx0 = fmaxf(mx0, fmaxf(sacc[n][0], sacc[n][1]));
                mx1 = fmaxf(mx1, fmaxf(sacc[n][2], sacc[n][3]));
            }
            mx0 = fmaxf(mx0, __shfl_xor_sync(0xffffffffu, mx0, 1));
            mx0 = fmaxf(mx0, __shfl_xor_sync(0xffffffffu, mx0, 2));
            mx1 = fmaxf(mx1, __shfl_xor_sync(0xffffffffu, mx1, 1));
            mx1 = fmaxf(mx1, __shfl_xor_sync(0xffffffffu, mx1, 2));

            const float mn0 = fmaxf(m0, mx0);
            const float mn1 = fmaxf(m1, mx1);
            const float cr0 = __expf(m0 - mn0);
            const float cr1 = __expf(m1 - mn1);
            float s0 = 0.f, s1 = 0.f;
            #pragma unroll
            for (int n = 0; n < 8; n++) {
                float p00 = __expf(sacc[n][0] - mn0);
                float p01 = __expf(sacc[n][1] - mn0);
                float p10 = __expf(sacc[n][2] - mn1);
                float p11 = __expf(sacc[n][3] - mn1);
                s0 += p00 + p01;
                s1 += p10 + p11;
                sacc[n][0] = p00; sacc[n][1] = p01;
                sacc[n][2] = p10; sacc[n][3] = p11;
            }
            s0 += __shfl_xor_sync(0xffffffffu, s0, 1);
            s0 += __shfl_xor_sync(0xffffffffu, s0, 2);
            s1 += __shfl_xor_sync(0xffffffffu, s1, 1);
            s1 += __shfl_xor_sync(0xffffffffu, s1, 2);

            l0 = l0 * cr0 + s0;  m0 = mn0;
            l1 = l1 * cr1 + s1;  m1 = mn1;
            #pragma unroll
            for (int n = 0; n < 8; n++) {
                o_acc[n][0] *= cr0; o_acc[n][1] *= cr0;
                o_acc[n][2] *= cr1; o_acc[n][3] *= cr1;
            }

            // O += P @ V : A-fragments packed from softmax registers
            #pragma unroll
            for (int j = 0; j < 4; j++) {
                const int kb = j * 16;
                uint32_t a0 = f2h2(sacc[2*j][0],   sacc[2*j][1]);
                uint32_t a1 = f2h2(sacc[2*j][2],   sacc[2*j][3]);
                uint32_t a2 = f2h2(sacc[2*j+1][0], sacc[2*j+1][1]);
                uint32_t a3 = f2h2(sacc[2*j+1][2], sacc[2*j+1][3]);
                uint32_t base = (uint32_t)__cvta_generic_to_shared(
                                    &Vt[(kb + (lane & 15)) * APH]);
                #pragma unroll
                for (int n = 0; n < 8; n++) {
                    uint32_t b0, b1;
                    ldsm_x2_trans(b0, b1, base + n * 16);
                    mma_f16(o_acc[n], a0, a1, a2, a3, b0, b1);
                }
            }
        }

        const float inv0 = 1.f / l0;
        const float inv1 = 1.f / l1;
        #pragma unroll
        for (int n = 0; n < 8; n++) {
            const int c0 = n * 8 + (lane & 3) * 2;
            size_t o0 = (size_t)(b * Sc + q0 + r0)     * OST + h * DHc + c0;
            size_t o1 = (size_t)(b * Sc + q0 + r0 + 8) * OST + h * DHc + c0;
            *(__half2*)&O[o0] = __floats2half2_rn(o_acc[n][0] * inv0, o_acc[n][1] * inv0);
            *(__half2*)&O[o1] = __floats2half2_rn(o_acc[n][2] * inv1, o_acc[n][3] * inv1);
        }
    }
}

// ---------------- LayerNorm over D=512 (single-pass reduction) ----------------
__global__ void ln_kernel(const float* __restrict__ X, const float* __restrict__ g,
                          const float* __restrict__ bta, float* __restrict__ Y,
                          __half* __restrict__ Yt) {
    int row = blockIdx.x;
    const float* x = X + (size_t)row * Dc;
    float*  y  = Y  + (size_t)row * Dc;
    __half* yt = Yt + (size_t)row * Dc;
    int tid = threadIdx.x;
    int d0  = tid * 4;

    float4 v = *(const float4*)(x + d0);
    float sum = v.x + v.y + v.z + v.w;
    float sq  = v.x*v.x + v.y*v.y + v.z*v.z + v.w*v.w;

    __shared__ float redS[4], redQ[4];
    #pragma unroll
    for (int off = 16; off; off >>= 1) {
        sum += __shfl_xor_sync(0xffffffffu, sum, off);
        sq  += __shfl_xor_sync(0xffffffffu, sq,  off);
    }
    if ((tid & 31) == 0) { redS[tid >> 5] = sum; redQ[tid >> 5] = sq; }
    __syncthreads();
    sum = redS[0] + redS[1] + redS[2] + redS[3];
    sq  = redQ[0] + redQ[1] + redQ[2] + redQ[3];
    float mean = sum * (1.f / Dc);
    float var  = sq * (1.f / Dc) - mean * mean;
    float rstd = rsqrtf(var + 1e-5f);

    float4 gg = *(const float4*)(g + d0);
    float4 bb = *(const float4*)(bta + d0);
    float4 o;
    o.x = (v.x - mean) * rstd * gg.x + bb.x;
    o.y = (v.y - mean) * rstd * gg.y + bb.y;
    o.z = (v.z - mean) * rstd * gg.z + bb.z;
    o.w = (v.w - mean) * rstd * gg.w + bb.w;
    *(float4*)(y + d0) = o;
    __half2 ho[2];
    ho[0] = __floats2half2_rn(o.x, o.y);
    ho[1] = __floats2half2_rn(o.z, o.w);
    *(uint2*)(yt + d0) = *(uint2*)ho;
}

// ---------------- launch ----------------------------------------------------
extern "C" void kernel_launch(void* const* d_in, const int* in_sizes, int n_in,
                              void* d_out, int out_size) {
    const int*   data = (const int*)  d_in[0];
    const float* we   = (const float*)d_in[1];
    const float* pe   = (const float*)d_in[2];
    const float* Wq   = (const float*)d_in[3];
    const float* Wkv  = (const float*)d_in[4];
    const float* Wo   = (const float*)d_in[5];
    const float* g1   = (const float*)d_in[6];
    const float* bl1  = (const float*)d_in[7];
    const float* W1   = (const float*)d_in[8];
    const float* bf1  = (const float*)d_in[9];
    const float* W2   = (const float*)d_in[10];
    const float* bf2  = (const float*)d_in[11];
    const float* g2   = (const float*)d_in[12];
    const float* bl2  = (const float*)d_in[13];
    const float* outb = (const float*)d_in[14];
    float* out = (float*)d_out;

    float *h, *tmp;
    __half *ht, *qkv, *aot, *fft;
    __half *wqkv, *wo_t, *w1_t, *w2_t, *we_t;
    cudaGetSymbolAddress((void**)&h,    g_h);
    cudaGetSymbolAddress((void**)&ht,   g_ht);
    cudaGetSymbolAddress((void**)&qkv,  g_qkv);
    cudaGetSymbolAddress((void**)&aot,  g_aot);
    cudaGetSymbolAddress((void**)&tmp,  g_tmp);
    cudaGetSymbolAddress((void**)&fft,  g_fft);
    cudaGetSymbolAddress((void**)&wqkv, g_wqkv);
    cudaGetSymbolAddress((void**)&wo_t, g_wo_t);
    cudaGetSymbolAddress((void**)&w1_t, g_w1_t);
    cudaGetSymbolAddress((void**)&w2_t, g_w2_t);
    cudaGetSymbolAddress((void**)&we_t, g_we_t);

    cudaFuncSetAttribute(fattn_tc, cudaFuncAttributeMaxDynamicSharedMemorySize, FATTN_SMEM);

    {
        int n8;
        n8 = Lc * QKVSTR * Dc / 8;  pack_qkv_w8<<<(n8 + 255)/256, 256>>>(Wq, Wkv, wqkv);
        n8 = Lc * Dc * Dc / 8;      cvt_w8<<<(n8 + 255)/256, 256>>>(Wo, wo_t, n8);
        n8 = Lc * DIc * Dc / 8;     cvt_w8<<<(n8 + 255)/256, 256>>>(W1, w1_t, n8);
        n8 = Lc * Dc * DIc / 8;     cvt_w8<<<(n8 + 255)/256, 256>>>(W2, w2_t, n8);
        n8 = Vc * Dc / 8;           cvt_w8<<<(n8 + 255)/256, 256>>>(we, we_t, n8);
    }

    embed_kernel<<<(M_ROWS*Dc/4 + 255)/256, 256>>>(data, we, pe, h, ht);

    dim3 g64D  ( Dc/128,     M_ROWS/64);
    dim3 g64QKV( QKVSTR/128, M_ROWS/64);
    dim3 g64DI ( DIc/128,    M_ROWS/64);
    dim3 gsV   ((Vc + 127)/128, M_ROWS/128);
    dim3 gsA   (NT64/2, Hc, Bc);            // 8 balanced pairs per (b,h)

    for (int l = 0; l < Lc; l++) {
        tgemm64_kernel<<<g64QKV, 256>>>(ht, wqkv + (size_t)l*QKVSTR*Dc, nullptr, nullptr,
                                        qkv, M_ROWS, QKVSTR, Dc, 0, 1);

        fattn_tc<<<gsA, 128, FATTN_SMEM>>>(qkv, qkv + Dc, qkv + 2*Dc, aot);

        tgemm64_kernel<<<g64D, 256>>>(aot, wo_t + (size_t)l*Dc*Dc, nullptr, h, tmp,
                                      M_ROWS, Dc, Dc, 0, 0);
        ln_kernel<<<M_ROWS, 128>>>(tmp, g1 + (size_t)l*Dc, bl1 + (size_t)l*Dc, h, ht);

        tgemm64_kernel<<<g64DI, 256>>>(ht, w1_t + (size_t)l*DIc*Dc, bf1 + (size_t)l*DIc, nullptr,
                                       fft, M_ROWS, DIc, Dc, 1, 1);
        tgemm64_kernel<<<g64D, 256>>>(fft, w2_t + (size_t)l*Dc*DIc, bf2 + (size_t)l*Dc, h,
                                      tmp, M_ROWS, Dc, DIc, 0, 0);
        ln_kernel<<<M_ROWS, 128>>>(tmp, g2 + (size_t)l*Dc, bl2 + (size_t)l*Dc, h, ht);
    }

    tgemm_kernel<<<gsV, 256>>>(ht, we_t, outb, nullptr, out, M_ROWS, Vc, Dc, 0, 0);
}

// round 15
// speedup vs baseline: 1.1127x; 1.0102x over previous
#include <cuda_runtime.h>
#include <cuda_fp16.h>
#include <math.h>
#include <stdint.h>

#define Bc 4
#define Sc 1024
#define Dc 512
#define Hc 8
#define DHc 64
#define DIc 2048
#define Lc 12
#define Vc 10000
#define M_ROWS (Bc*Sc)   /* 4096 */
#define QKVSTR (3*Dc)    /* 1536 */

// ---------------- scratch (no allocations allowed) ----------------
__device__ float  g_h   [M_ROWS*Dc];
__device__ __half g_ht  [M_ROWS*Dc];
__device__ __half g_qkv [M_ROWS*QKVSTR];
__device__ __half g_aot [M_ROWS*Dc];
__device__ float  g_tmp [M_ROWS*Dc];
__device__ __half g_fft [M_ROWS*DIc];
__device__ __half g_wqkv[Lc*QKVSTR*Dc];
__device__ __half g_wo_t[Lc*Dc*Dc];
__device__ __half g_w1_t[Lc*DIc*Dc];
__device__ __half g_w2_t[Lc*Dc*DIc];
__device__ __half g_we_t[Vc*Dc];

// ---------------- helpers ----------------------------------------------------
__device__ __forceinline__ void cp16(void* smem, const void* g, int srcBytes) {
    uint32_t s = (uint32_t)__cvta_generic_to_shared(smem);
    asm volatile("cp.async.cg.shared.global [%0], [%1], 16, %2;\n"
                 :: "r"(s), "l"(g), "r"(srcBytes));
}

__device__ __forceinline__ void mma_f16(float c[4],
    uint32_t a0, uint32_t a1, uint32_t a2, uint32_t a3,
    uint32_t b0, uint32_t b1)
{
    asm volatile(
        "mma.sync.aligned.m16n8k16.row.col.f32.f16.f16.f32 "
        "{%0,%1,%2,%3}, {%4,%5,%6,%7}, {%8,%9}, {%0,%1,%2,%3};"
        : "+f"(c[0]), "+f"(c[1]), "+f"(c[2]), "+f"(c[3])
        : "r"(a0), "r"(a1), "r"(a2), "r"(a3), "r"(b0), "r"(b1));
}

__device__ __forceinline__ void ldsm_x4(uint32_t& r0, uint32_t& r1,
                                        uint32_t& r2, uint32_t& r3, uint32_t addr) {
    asm volatile("ldmatrix.sync.aligned.m8n8.x4.shared.b16 {%0,%1,%2,%3}, [%4];"
                 : "=r"(r0), "=r"(r1), "=r"(r2), "=r"(r3) : "r"(addr));
}

__device__ __forceinline__ void ldsm_x4_trans(uint32_t& r0, uint32_t& r1,
                                              uint32_t& r2, uint32_t& r3, uint32_t addr) {
    asm volatile("ldmatrix.sync.aligned.m8n8.x4.trans.shared.b16 {%0,%1,%2,%3}, [%4];"
                 : "=r"(r0), "=r"(r1), "=r"(r2), "=r"(r3) : "r"(addr));
}

__device__ __forceinline__ uint32_t f2h2(float a, float b) {
    __half2 h = __floats2half2_rn(a, b);
    return *(uint32_t*)&h;
}

// ---------------- weight preconversion (vectorized) ---------------------------
__global__ void pack_qkv_w8(const float* __restrict__ Wq, const float* __restrict__ Wkv,
                            __half* __restrict__ dst) {
    int i = blockIdx.x * blockDim.x + threadIdx.x;
    const int NC8 = Dc / 8;
    if (i >= Lc * QKVSTR * NC8) return;
    int c8 = (i % NC8) * 8;
    int r  = (i / NC8) % QKVSTR;
    int l  = i / (NC8 * QKVSTR);
    const float* src;
    float sc;
    if (r < Dc) { src = Wq  + ((size_t)l * Dc + r) * Dc + c8;              sc = 0.125f; }
    else        { src = Wkv + ((size_t)l * 2 * Dc + (r - Dc)) * Dc + c8;   sc = 1.f; }
    float4 x = *(const float4*)src;
    float4 y = *(const float4*)(src + 4);
    __half2 o[4];
    o[0] = __floats2half2_rn(x.x * sc, x.y * sc);
    o[1] = __floats2half2_rn(x.z * sc, x.w * sc);
    o[2] = __floats2half2_rn(y.x * sc, y.y * sc);
    o[3] = __floats2half2_rn(y.z * sc, y.w * sc);
    *(uint4*)&dst[(size_t)i * 8] = *(uint4*)o;
}

__global__ void cvt_w8(const float* __restrict__ src, __half* __restrict__ dst, int n8) {
    int i = blockIdx.x * blockDim.x + threadIdx.x;
    if (i >= n8) return;
    float4 x = *(const float4*)(src + (size_t)i * 8);
    float4 y = *(const float4*)(src + (size_t)i * 8 + 4);
    __half2 o[4];
    o[0] = __floats2half2_rn(x.x, x.y);
    o[1] = __floats2half2_rn(x.z, x.w);
    o[2] = __floats2half2_rn(y.x, y.y);
    o[3] = __floats2half2_rn(y.z, y.w);
    *(uint4*)&dst[(size_t)i * 8] = *(uint4*)o;
}

// ---------------- embedding (4 elems/thread) ----------------
__global__ void embed_kernel(const int* __restrict__ data,
                             const float* __restrict__ we,
                             const float* __restrict__ pe,
                             float* __restrict__ h, __half* __restrict__ ht) {
    int i = blockIdx.x * blockDim.x + threadIdx.x;
    if (i >= M_ROWS * Dc / 4) return;
    int d4  = (i % (Dc / 4)) * 4;
    int row = i / (Dc / 4);
    int s   = row % Sc;
    int tok = data[row];
    float4 a = *(const float4*)(we + (size_t)tok * Dc + d4);
    float4 p = *(const float4*)(pe + (size_t)s   * Dc + d4);
    float4 v = make_float4(a.x + p.x, a.y + p.y, a.z + p.z, a.w + p.w);
    *(float4*)&h[(size_t)row * Dc + d4] = v;
    __half2 o[2];
    o[0] = __floats2half2_rn(v.x, v.y);
    o[1] = __floats2half2_rn(v.z, v.w);
    *(uint2*)&ht[(size_t)row * Dc + d4] = *(uint2*)o;
}

// ============ tgemm64: TBM=64, TBN=128, 3-stage pipeline, 1 sync/iter =========
#define T2M 64
#define T2N 128
#define T2K 32
#define TP 40

__global__ __launch_bounds__(256) void tgemm64_kernel(
    const __half* __restrict__ A, const __half* __restrict__ W,
    const float* __restrict__ bias, const float* __restrict__ res,
    void* __restrict__ Cv, int M, int N, int K, int doRelu, int outMode)
{
    __shared__ __align__(16) __half As[3][T2M][TP];
    __shared__ __align__(16) __half Bs[3][T2N][TP];

    const int tid  = threadIdx.x;
    const int lane = tid & 31;
    const int warp = tid >> 5;
    const int wm   = warp >> 2;
    const int wn   = warp & 3;
    const int bm   = blockIdx.y * T2M;
    const int bn   = blockIdx.x * T2N;

    const uint32_t asBase = (uint32_t)__cvta_generic_to_shared(&As[0][0][0]);
    const uint32_t bsBase = (uint32_t)__cvta_generic_to_shared(&Bs[0][0][0]);

    float acc[2][4][4];
    #pragma unroll
    for (int i = 0; i < 2; i++)
        #pragma unroll
        for (int j = 0; j < 4; j++)
            #pragma unroll
            for (int t = 0; t < 4; t++) acc[i][j][t] = 0.f;

    const int KT = K / T2K;
    const int rA  = tid >> 2, hA = (tid & 3) * 8;

    #pragma unroll
    for (int s = 0; s < 2; s++) {
        int k0 = s * T2K;
        cp16(&As[s][rA][hA], A + (size_t)(bm + rA) * K + k0 + hA, 16);
        #pragma unroll
        for (int p = 0; p < 2; p++) {
            int c = tid + p * 256;
            int r = c >> 2, hf = (c & 3) * 8;
            cp16(&Bs[s][r][hf], W + (size_t)(bn + r) * K + k0 + hf, 16);
        }
        asm volatile("cp.async.commit_group;\n");
    }

    const int r8  = lane & 7;
    const int sel = lane >> 3;

    for (int t = 0; t < KT; t++) {
        asm volatile("cp.async.wait_group 1;\n");
        __syncthreads();

        {
            int tp = t + 2;
            if (tp < KT) {
                int sb = tp % 3;
                int k0 = tp * T2K;
                cp16(&As[sb][rA][hA], A + (size_t)(bm + rA) * K + k0 + hA, 16);
                #pragma unroll
                for (int p = 0; p < 2; p++) {
                    int c = tid + p * 256;
                    int r = c >> 2, hf = (c & 3) * 8;
                    cp16(&Bs[sb][r][hf], W + (size_t)(bn + r) * K + k0 + hf, 16);
                }
            }
            asm volatile("cp.async.commit_group;\n");
        }

        const int buf = t % 3;
        #pragma unroll
        for (int ks = 0; ks < 2; ks++) {
            const int kb = ks * 16;
            uint32_t af[2][4], bf[4][2];
            #pragma unroll
            for (int mi = 0; mi < 2; mi++) {
                int row  = wm * 32 + mi * 16 + r8 + ((sel & 1) << 3);
                int colh = kb + ((sel >> 1) << 3);
                uint32_t addr = asBase + (((buf * T2M + row) * TP + colh) << 1);
                ldsm_x4(af[mi][0], af[mi][1], af[mi][2], af[mi][3], addr);
            }
            #pragma unroll
            for (int nj = 0; nj < 2; nj++) {
                int row  = wn * 32 + nj * 16 + r8 + ((sel >> 1) << 3);
                int colh = kb + ((sel & 1) << 3);
                uint32_t addr = bsBase + (((buf * T2N + row) * TP + colh) << 1);
                ldsm_x4(bf[nj*2][0], bf[nj*2][1], bf[nj*2+1][0], bf[nj*2+1][1], addr);
            }
            #pragma unroll
            for (int mi = 0; mi < 2; mi++)
                #pragma unroll
                for (int ni = 0; ni < 4; ni++)
                    mma_f16(acc[mi][ni], af[mi][0], af[mi][1], af[mi][2], af[mi][3],
                            bf[ni][0], bf[ni][1]);
        }
    }

    const int lr = lane >> 2;
    const int lc = (lane & 3) * 2;
    #pragma unroll
    for (int mi = 0; mi < 2; mi++) {
        int r0 = bm + wm * 32 + mi * 16 + lr;
        #pragma unroll
        for (int ni = 0; ni < 4; ni++) {
            int c0 = bn + wn * 32 + ni * 8 + lc;
            float v0 = acc[mi][ni][0], v1 = acc[mi][ni][1];
            float v2 = acc[mi][ni][2], v3 = acc[mi][ni][3];
            if (bias) {
                float b0 = bias[c0], b1 = bias[c0 + 1];
                v0 += b0; v1 += b1; v2 += b0; v3 += b1;
            }
            if (res) {
                v0 += res[(size_t)r0 * N + c0];
                v1 += res[(size_t)r0 * N + c0 + 1];
                v2 += res[(size_t)(r0 + 8) * N + c0];
                v3 += res[(size_t)(r0 + 8) * N + c0 + 1];
            }
            if (doRelu) {
                v0 = fmaxf(v0, 0.f); v1 = fmaxf(v1, 0.f);
                v2 = fmaxf(v2, 0.f); v3 = fmaxf(v3, 0.f);
            }
            if (outMode == 0) {
                float* C = (float*)Cv;
                *(float2*)&C[(size_t)r0 * N + c0]       = make_float2(v0, v1);
                *(float2*)&C[(size_t)(r0 + 8) * N + c0] = make_float2(v2, v3);
            } else {
                __half* C = (__half*)Cv;
                *(__half2*)&C[(size_t)r0 * N + c0]       = __floats2half2_rn(v0, v1);
                *(__half2*)&C[(size_t)(r0 + 8) * N + c0] = __floats2half2_rn(v2, v3);
            }
        }
    }
}

// ============ tgemm128: proven 128x128 TBK=32 kernel (logits) ================
#define TBM 128
#define TBN 128
#define TBK 32

__global__ __launch_bounds__(256) void tgemm_kernel(
    const __half* __restrict__ A, const __half* __restrict__ W,
    const float* __restrict__ bias, const float* __restrict__ res,
    void* __restrict__ Cv, int M, int N, int K, int doRelu, int outMode)
{
    __shared__ __align__(16) __half As[2][TBM][TP];
    __shared__ __align__(16) __half Bs[2][TBN][TP];

    const int tid  = threadIdx.x;
    const int lane = tid & 31;
    const int warp = tid >> 5;
    const int wm   = warp >> 2;
    const int wn   = warp & 3;
    const int bm   = blockIdx.y * TBM;
    const int bn   = blockIdx.x * TBN;

    const uint32_t asBase = (uint32_t)__cvta_generic_to_shared(&As[0][0][0]);
    const uint32_t bsBase = (uint32_t)__cvta_generic_to_shared(&Bs[0][0][0]);

    float acc[4][4][4];
    #pragma unroll
    for (int i = 0; i < 4; i++)
        #pragma unroll
        for (int j = 0; j < 4; j++)
            #pragma unroll
            for (int t = 0; t < 4; t++) acc[i][j][t] = 0.f;

    const int KT = K / TBK;

    #pragma unroll
    for (int p = 0; p < 2; p++) {
        int c = tid + p * 256;
        int r = c >> 2, hoff = (c & 3) * 8;
        cp16(&As[0][r][hoff], A + (size_t)(bm + r) * K + hoff, 16);
        int gn = bn + r;
        int ok = (gn < N) ? 16 : 0;
        int gc = (gn < N) ? gn : (N - 1);
        cp16(&Bs[0][r][hoff], W + (size_t)gc * K + hoff, ok);
    }
    asm volatile("cp.async.commit_group;\n");

    const int r8  = lane & 7;
    const int sel = lane >> 3;

    for (int t = 0; t < KT; t++) {
        asm volatile("cp.async.wait_group 0;\n");
        __syncthreads();

        if (t + 1 < KT) {
            int nb = (t + 1) & 1;
            int k0 = (t + 1) * TBK;
            #pragma unroll
            for (int p = 0; p < 2; p++) {
                int c = tid + p * 256;
                int r = c >> 2, hoff = (c & 3) * 8;
                cp16(&As[nb][r][hoff], A + (size_t)(bm + r) * K + k0 + hoff, 16);
                int gn = bn + r;
                int ok = (gn < N) ? 16 : 0;
                int gc = (gn < N) ? gn : (N - 1);
                cp16(&Bs[nb][r][hoff], W + (size_t)gc * K + k0 + hoff, ok);
            }
            asm volatile("cp.async.commit_group;\n");
        }

        const int buf = t & 1;
        #pragma unroll
        for (int ks = 0; ks < 2; ks++) {
            const int kb = ks * 16;
            uint32_t af[4][4], bf[4][2];
            #pragma unroll
            for (int mi = 0; mi < 4; mi++) {
                int row  = wm * 64 + mi * 16 + r8 + ((sel & 1) << 3);
                int colh = kb + ((sel >> 1) << 3);
                uint32_t addr = asBase + (((buf * TBM + row) * TP + colh) << 1);
                ldsm_x4(af[mi][0], af[mi][1], af[mi][2], af[mi][3], addr);
            }
            #pragma unroll
            for (int nj = 0; nj < 2; nj++) {
                int row  = wn * 32 + nj * 16 + r8 + ((sel >> 1) << 3);
                int colh = kb + ((sel & 1) << 3);
                uint32_t addr = bsBase + (((buf * TBN + row) * TP + colh) << 1);
                ldsm_x4(bf[nj*2][0], bf[nj*2][1], bf[nj*2+1][0], bf[nj*2+1][1], addr);
            }
            #pragma unroll
            for (int mi = 0; mi < 4; mi++)
                #pragma unroll
                for (int ni = 0; ni < 4; ni++)
                    mma_f16(acc[mi][ni], af[mi][0], af[mi][1], af[mi][2], af[mi][3],
                            bf[ni][0], bf[ni][1]);
        }
        __syncthreads();
    }

    const int lr = lane >> 2;
    const int lc = (lane & 3) * 2;
    #pragma unroll
    for (int mi = 0; mi < 4; mi++) {
        int r0 = bm + wm * 64 + mi * 16 + lr;
        #pragma unroll
        for (int ni = 0; ni < 4; ni++) {
            int c0 = bn + wn * 32 + ni * 8 + lc;
            if (c0 >= N) continue;
            float v0 = acc[mi][ni][0], v1 = acc[mi][ni][1];
            float v2 = acc[mi][ni][2], v3 = acc[mi][ni][3];
            if (bias) {
                float b0 = bias[c0], b1 = bias[c0 + 1];
                v0 += b0; v1 += b1; v2 += b0; v3 += b1;
            }
            if (res) {
                v0 += res[(size_t)r0 * N + c0];
                v1 += res[(size_t)r0 * N + c0 + 1];
                v2 += res[(size_t)(r0 + 8) * N + c0];
                v3 += res[(size_t)(r0 + 8) * N + c0 + 1];
            }
            if (doRelu) {
                v0 = fmaxf(v0, 0.f); v1 = fmaxf(v1, 0.f);
                v2 = fmaxf(v2, 0.f); v3 = fmaxf(v3, 0.f);
            }
            if (outMode == 0) {
                float* C = (float*)Cv;
                *(float2*)&C[(size_t)r0 * N + c0]       = make_float2(v0, v1);
                *(float2*)&C[(size_t)(r0 + 8) * N + c0] = make_float2(v2, v3);
            } else {
                __half* C = (__half*)Cv;
                *(__half2*)&C[(size_t)r0 * N + c0]       = __floats2half2_rn(v0, v1);
                *(__half2*)&C[(size_t)(r0 + 8) * N + c0] = __floats2half2_rn(v2, v3);
            }
        }
    }
}

// ---------------- fp16 flash attention: balanced pairs, ldsm everywhere -------
#define APH 72
#define NT64 (Sc/64)
#define FATTN_SMEM ((64 + 128 + 128) * APH * 2)

extern __shared__ __half attn_smem[];

__global__ __launch_bounds__(128) void fattn_tc(
    const __half* __restrict__ Q, const __half* __restrict__ Kb,
    const __half* __restrict__ Vb, __half* __restrict__ O)
{
    __half* Qs = attn_smem;               // [64][APH]
    __half* Ks = Qs + 64 * APH;           // 2 x [64][APH]
    __half* Vk = Ks + 2 * 64 * APH;       // 2 x [64][APH]

    const int qpair = blockIdx.x;         // 0..7
    const int h  = blockIdx.y, b = blockIdx.z;
    const int tid  = threadIdx.x;
    const int lane = tid & 31;
    const int warp = tid >> 5;            // 0..3

    const int OST = Hc * DHc;

    const int r0   = warp * 16 + (lane >> 2);
    const int r8   = lane & 7;
    const int sel  = lane >> 3;
    const uint32_t qsBase = (uint32_t)__cvta_generic_to_shared(Qs);
    const uint32_t ksBase = (uint32_t)__cvta_generic_to_shared(Ks);
    const uint32_t vkBase = (uint32_t)__cvta_generic_to_shared(Vk);

    const size_t kvrow0 = (size_t)(b * Sc) * QKVSTR + h * DHc;

    // V ldsm.x4.trans lane addressing (row within kv tile, col-octet select)
    const int vrow = ((lane >> 3) & 1) * 8 + (lane & 7);   // 0..15
    const int vsel = lane >> 4;                            // 0..1

    #pragma unroll
    for (int seg = 0; seg < 2; seg++) {
        const int qt = seg ? (NT64 - 1 - qpair) : qpair;
        const int q0 = qt * 64;

        __syncthreads();   // prior segment's smem reads complete before overwrite

        // load Q tile: 64 rows x 128B
        #pragma unroll
        for (int p = 0; p < 4; p++) {
            int c = tid + p * 128;
            int r = c >> 3, d8 = (c & 7) * 8;
            float4 v = *(const float4*)(Q + (size_t)(b * Sc + q0 + r) * QKVSTR + h * DHc + d8);
            *(float4*)&Qs[r * APH + d8] = v;
        }

        // prologue: kv tile 0
        #pragma unroll
        for (int p = 0; p < 4; p++) {
            int c = tid + p * 128;
            int r = c >> 3, d8 = (c & 7) * 8;
            cp16(&Ks[r * APH + d8], Kb + kvrow0 + (size_t)r * QKVSTR + d8, 16);
            cp16(&Vk[r * APH + d8], Vb + kvrow0 + (size_t)r * QKVSTR + d8, 16);
        }
        asm volatile("cp.async.commit_group;\n");

        __syncthreads();   // Q stores visible for ldmatrix

        // hoist Q fragments (loop-invariant over kv tiles)
        uint32_t qf[4][4];
        #pragma unroll
        for (int ks = 0; ks < 4; ks++) {
            int row  = warp * 16 + r8 + ((sel & 1) << 3);
            int colh = ks * 16 + ((sel >> 1) << 3);
            ldsm_x4(qf[ks][0], qf[ks][1], qf[ks][2], qf[ks][3],
                    qsBase + ((row * APH + colh) << 1));
        }

        float o_acc[8][4];
        #pragma unroll
        for (int n = 0; n < 8; n++)
            #pragma unroll
            for (int t = 0; t < 4; t++) o_acc[n][t] = 0.f;
        float m0 = -1e30f, m1 = -1e30f, l0 = 0.f, l1 = 0.f;

        const int nt = qt + 1;

        for (int kt = 0; kt < nt; kt++) {
            asm volatile("cp.async.wait_group 0;\n");
            __syncthreads();

            const int buf = kt & 1;
            if (kt + 1 < nt) {
                const int nb = buf ^ 1;
                const size_t base = kvrow0 + (size_t)(kt + 1) * 64 * QKVSTR;
                #pragma unroll
                for (int p = 0; p < 4; p++) {
                    int c = tid + p * 128;
                    int r = c >> 3, d8 = (c & 7) * 8;
                    cp16(&Ks[nb * 64 * APH + r * APH + d8], Kb + base + (size_t)r * QKVSTR + d8, 16);
                    cp16(&Vk[nb * 64 * APH + r * APH + d8], Vb + base + (size_t)r * QKVSTR + d8, 16);
                }
            }
            asm volatile("cp.async.commit_group;\n");

            const uint32_t ktBase = ksBase + ((buf * 64 * APH) << 1);
            const uint32_t vtBase = vkBase + ((buf * 64 * APH) << 1);

            // S = Q @ K^T (K fragments via ldsm.x4)
            float sacc[8][4];
            #pragma unroll
            for (int n = 0; n < 8; n++)
                #pragma unroll
                for (int t = 0; t < 4; t++) sacc[n][t] = 0.f;

            #pragma unroll
            for (int ks = 0; ks < 4; ks++) {
                const int kb = ks * 16;
                #pragma unroll
                for (int ng = 0; ng < 4; ng++) {
                    int row  = ng * 16 + r8 + ((sel >> 1) << 3);
                    int colh = kb + ((sel & 1) << 3);
                    uint32_t b00, b01, b10, b11;
                    ldsm_x4(b00, b01, b10, b11, ktBase + ((row * APH + colh) << 1));
                    mma_f16(sacc[2*ng],   qf[ks][0], qf[ks][1], qf[ks][2], qf[ks][3], b00, b01);
                    mma_f16(sacc[2*ng+1], qf[ks][0], qf[ks][1], qf[ks][2], qf[ks][3], b10, b11);
                }
            }

            if (kt == qt) {   // diagonal tile: causal mask
                #pragma unroll
                for (int n = 0; n < 8; n++) {
                    const int c0 = n * 8 + (lane & 3) * 2;
                    if (c0     > r0)     sacc[n][0] = -1e30f;
                    if (c0 + 1 > r0)     sacc[n][1] = -1e30f;
                    if (c0     > r0 + 8) sacc[n][2] = -1e30f;
                    if (c0 + 1 > r0 + 8) sacc[n][3] = -1e30f;
                }
            }

            float mx0 = -1e30f, mx1 = -1e30f;
            #pragma unroll
            for (int n = 0; n < 8; n++) {
                mx0 = fmaxf(mx0, fmaxf(sacc[n][0], sacc[n][1]));
                mx1 = fmaxf(mx1, fmaxf(sacc[n][2], sacc[n][3]));
            }
            mx0 = fmaxf(mx0, __shfl_xor_sync(0xffffffffu, mx0, 1));
            mx0 = fmaxf(mx0, __shfl_xor_sync(0xffffffffu, mx0, 2));
            mx1 = fmaxf(mx1, __shfl_xor_sync(0xffffffffu, mx1, 1));
            mx1 = fmaxf(mx1, __shfl_xor_sync(0xffffffffu, mx1, 2));

            const float mn0 = fmaxf(m0, mx0);
            const float mn1 = fmaxf(m1, mx1);
            const float cr0 = __expf(m0 - mn0);
            const float cr1 = __expf(m1 - mn1);
            float s0 = 0.f, s1 = 0.f;
            #pragma unroll
            for (int n = 0; n < 8; n++) {
                float p00 = __expf(sacc[n][0] - mn0);
                float p01 = __expf(sacc[n][1] - mn0);
                float p10 = __expf(sacc[n][2] - mn1);
                float p11 = __expf(sacc[n][3] - mn1);
                s0 += p00 + p01;
                s1 += p10 + p11;
                sacc[n][0] = p00; sacc[n][1] = p01;
                sacc[n][2] = p10; sacc[n][3] = p11;
            }
            s0 += __shfl_xor_sync(0xffffffffu, s0, 1);
            s0 += __shfl_xor_sync(0xffffffffu, s0, 2);
            s1 += __shfl_xor_sync(0xffffffffu, s1, 1);
            s1 += __shfl_xor_sync(0xffffffffu, s1, 2);

            l0 = l0 * cr0 + s0;  m0 = mn0;
            l1 = l1 * cr1 + s1;  m1 = mn1;
            #pragma unroll
            for (int n = 0; n < 8; n++) {
                o_acc[n][0] *= cr0; o_acc[n][1] *= cr0;
                o_acc[n][2] *= cr1; o_acc[n][3] *= cr1;
            }

            // O += P @ V : A from registers, B via ldsm.x4.trans (2 n-octets/op)
            #pragma unroll
            for (int j = 0; j < 4; j++) {
                const int kb = j * 16;
                uint32_t a0 = f2h2(sacc[2*j][0],   sacc[2*j][1]);
                uint32_t a1 = f2h2(sacc[2*j][2],   sacc[2*j][3]);
                uint32_t a2 = f2h2(sacc[2*j+1][0], sacc[2*j+1][1]);
                uint32_t a3 = f2h2(sacc[2*j+1][2], sacc[2*j+1][3]);
                #pragma unroll
                for (int n2 = 0; n2 < 4; n2++) {
                    const int row  = kb + vrow;
                    const int col8 = (n2 * 2 + vsel) * 8;
                    uint32_t b0, b1, b2, b3;
                    ldsm_x4_trans(b0, b1, b2, b3, vtBase + ((row * APH + col8) << 1));
                    mma_f16(o_acc[2*n2],   a0, a1, a2, a3, b0, b1);
                    mma_f16(o_acc[2*n2+1], a0, a1, a2, a3, b2, b3);
                }
            }
        }

        const float inv0 = 1.f / l0;
        const float inv1 = 1.f / l1;
        #pragma unroll
        for (int n = 0; n < 8; n++) {
            const int c0 = n * 8 + (lane & 3) * 2;
            size_t o0 = (size_t)(b * Sc + q0 + r0)     * OST + h * DHc + c0;
            size_t o1 = (size_t)(b * Sc + q0 + r0 + 8) * OST + h * DHc + c0;
            *(__half2*)&O[o0] = __floats2half2_rn(o_acc[n][0] * inv0, o_acc[n][1] * inv0);
            *(__half2*)&O[o1] = __floats2half2_rn(o_acc[n][2] * inv1, o_acc[n][3] * inv1);
        }
    }
}

// ---------------- LayerNorm over D=512 (single-pass reduction) ----------------
__global__ void ln_kernel(const float* __restrict__ X, const float* __restrict__ g,
                          const float* __restrict__ bta, float* __restrict__ Y,
                          __half* __restrict__ Yt) {
    int row = blockIdx.x;
    const float* x = X + (size_t)row * Dc;
    float*  y  = Y  + (size_t)row * Dc;
    __half* yt = Yt + (size_t)row * Dc;
    int tid = threadIdx.x;
    int d0  = tid * 4;

    float4 v = *(const float4*)(x + d0);
    float sum = v.x + v.y + v.z + v.w;
    float sq  = v.x*v.x + v.y*v.y + v.z*v.z + v.w*v.w;

    __shared__ float redS[4], redQ[4];
    #pragma unroll
    for (int off = 16; off; off >>= 1) {
        sum += __shfl_xor_sync(0xffffffffu, sum, off);
        sq  += __shfl_xor_sync(0xffffffffu, sq,  off);
    }
    if ((tid & 31) == 0) { redS[tid >> 5] = sum; redQ[tid >> 5] = sq; }
    __syncthreads();
    sum = redS[0] + redS[1] + redS[2] + redS[3];
    sq  = redQ[0] + redQ[1] + redQ[2] + redQ[3];
    float mean = sum * (1.f / Dc);
    float var  = sq * (1.f / Dc) - mean * mean;
    float rstd = rsqrtf(var + 1e-5f);

    float4 gg = *(const float4*)(g + d0);
    float4 bb = *(const float4*)(bta + d0);
    float4 o;
    o.x = (v.x - mean) * rstd * gg.x + bb.x;
    o.y = (v.y - mean) * rstd * gg.y + bb.y;
    o.z = (v.z - mean) * rstd * gg.z + bb.z;
    o.w = (v.w - mean) * rstd * gg.w + bb.w;
    *(float4*)(y + d0) = o;
    __half2 ho[2];
    ho[0] = __floats2half2_rn(o.x, o.y);
    ho[1] = __floats2half2_rn(o.z, o.w);
    *(uint2*)(yt + d0) = *(uint2*)ho;
}

// ---------------- launch ----------------------------------------------------
extern "C" void kernel_launch(void* const* d_in, const int* in_sizes, int n_in,
                              void* d_out, int out_size) {
    const int*   data = (const int*)  d_in[0];
    const float* we   = (const float*)d_in[1];
    const float* pe   = (const float*)d_in[2];
    const float* Wq   = (const float*)d_in[3];
    const float* Wkv  = (const float*)d_in[4];
    const float* Wo   = (const float*)d_in[5];
    const float* g1   = (const float*)d_in[6];
    const float* bl1  = (const float*)d_in[7];
    const float* W1   = (const float*)d_in[8];
    const float* bf1  = (const float*)d_in[9];
    const float* W2   = (const float*)d_in[10];
    const float* bf2  = (const float*)d_in[11];
    const float* g2   = (const float*)d_in[12];
    const float* bl2  = (const float*)d_in[13];
    const float* outb = (const float*)d_in[14];
    float* out = (float*)d_out;

    float *h, *tmp;
    __half *ht, *qkv, *aot, *fft;
    __half *wqkv, *wo_t, *w1_t, *w2_t, *we_t;
    cudaGetSymbolAddress((void**)&h,    g_h);
    cudaGetSymbolAddress((void**)&ht,   g_ht);
    cudaGetSymbolAddress((void**)&qkv,  g_qkv);
    cudaGetSymbolAddress((void**)&aot,  g_aot);
    cudaGetSymbolAddress((void**)&tmp,  g_tmp);
    cudaGetSymbolAddress((void**)&fft,  g_fft);
    cudaGetSymbolAddress((void**)&wqkv, g_wqkv);
    cudaGetSymbolAddress((void**)&wo_t, g_wo_t);
    cudaGetSymbolAddress((void**)&w1_t, g_w1_t);
    cudaGetSymbolAddress((void**)&w2_t, g_w2_t);
    cudaGetSymbolAddress((void**)&we_t, g_we_t);

    cudaFuncSetAttribute(fattn_tc, cudaFuncAttributeMaxDynamicSharedMemorySize, FATTN_SMEM);

    {
        int n8;
        n8 = Lc * QKVSTR * Dc / 8;  pack_qkv_w8<<<(n8 + 255)/256, 256>>>(Wq, Wkv, wqkv);
        n8 = Lc * Dc * Dc / 8;      cvt_w8<<<(n8 + 255)/256, 256>>>(Wo, wo_t, n8);
        n8 = Lc * DIc * Dc / 8;     cvt_w8<<<(n8 + 255)/256, 256>>>(W1, w1_t, n8);
        n8 = Lc * Dc * DIc / 8;     cvt_w8<<<(n8 + 255)/256, 256>>>(W2, w2_t, n8);
        n8 = Vc * Dc / 8;           cvt_w8<<<(n8 + 255)/256, 256>>>(we, we_t, n8);
    }

    embed_kernel<<<(M_ROWS*Dc/4 + 255)/256, 256>>>(data, we, pe, h, ht);

    dim3 g64D  ( Dc/128,     M_ROWS/64);
    dim3 g64QKV( QKVSTR/128, M_ROWS/64);
    dim3 g64DI ( DIc/128,    M_ROWS/64);
    dim3 gsV   ((Vc + 127)/128, M_ROWS/128);
    dim3 gsA   (NT64/2, Hc, Bc);

    for (int l = 0; l < Lc; l++) {
        tgemm64_kernel<<<g64QKV, 256>>>(ht, wqkv + (size_t)l*QKVSTR*Dc, nullptr, nullptr,
                                        qkv, M_ROWS, QKVSTR, Dc, 0, 1);

        fattn_tc<<<gsA, 128, FATTN_SMEM>>>(qkv, qkv + Dc, qkv + 2*Dc, aot);

        tgemm64_kernel<<<g64D, 256>>>(aot, wo_t + (size_t)l*Dc*Dc, nullptr, h, tmp,
                                      M_ROWS, Dc, Dc, 0, 0);
        ln_kernel<<<M_ROWS, 128>>>(tmp, g1 + (size_t)l*Dc, bl1 + (size_t)l*Dc, h, ht);

        tgemm64_kernel<<<g64DI, 256>>>(ht, w1_t + (size_t)l*DIc*Dc, bf1 + (size_t)l*DIc, nullptr,
                                       fft, M_ROWS, DIc, Dc, 1, 1);
        tgemm64_kernel<<<g64D, 256>>>(fft, w2_t + (size_t)l*Dc*DIc, bf2 + (size_t)l*Dc, h,
                                      tmp, M_ROWS, Dc, DIc, 0, 0);
        ln_kernel<<<M_ROWS, 128>>>(tmp, g2 + (size_t)l*Dc, bl2 + (size_t)l*Dc, h, ht);
    }

    tgemm_kernel<<<gsV, 256>>>(ht, we_t, outb, nullptr, out, M_ROWS, Vc, Dc, 0, 0);
}

// round 16
// speedup vs baseline: 1.1375x; 1.0223x over previous
#include <cuda_runtime.h>
#include <cuda_fp16.h>
#include <math.h>
#include <stdint.h>

#define Bc 4
#define Sc 1024
#define Dc 512
#define Hc 8
#define DHc 64
#define DIc 2048
#define Lc 12
#define Vc 10000
#define M_ROWS (Bc*Sc)   /* 4096 */
#define QKVSTR (3*Dc)    /* 1536 */

// ---------------- scratch (no allocations allowed) ----------------
__device__ float  g_h   [M_ROWS*Dc];
__device__ __half g_ht  [M_ROWS*Dc];
__device__ __half g_qkv [M_ROWS*QKVSTR];
__device__ __half g_aot [M_ROWS*Dc];
__device__ float  g_tmp [M_ROWS*Dc];
__device__ __half g_fft [M_ROWS*DIc];
__device__ __half g_wqkv[Lc*QKVSTR*Dc];
__device__ __half g_wo_t[Lc*Dc*Dc];
__device__ __half g_w1_t[Lc*DIc*Dc];
__device__ __half g_w2_t[Lc*Dc*DIc];
__device__ __half g_we_t[Vc*Dc];

// ---------------- helpers ----------------------------------------------------
__device__ __forceinline__ void cp16(void* smem, const void* g, int srcBytes) {
    uint32_t s = (uint32_t)__cvta_generic_to_shared(smem);
    asm volatile("cp.async.cg.shared.global [%0], [%1], 16, %2;\n"
                 :: "r"(s), "l"(g), "r"(srcBytes));
}

__device__ __forceinline__ void mma_f16(float c[4],
    uint32_t a0, uint32_t a1, uint32_t a2, uint32_t a3,
    uint32_t b0, uint32_t b1)
{
    asm volatile(
        "mma.sync.aligned.m16n8k16.row.col.f32.f16.f16.f32 "
        "{%0,%1,%2,%3}, {%4,%5,%6,%7}, {%8,%9}, {%0,%1,%2,%3};"
        : "+f"(c[0]), "+f"(c[1]), "+f"(c[2]), "+f"(c[3])
        : "r"(a0), "r"(a1), "r"(a2), "r"(a3), "r"(b0), "r"(b1));
}

__device__ __forceinline__ void ldsm_x4(uint32_t& r0, uint32_t& r1,
                                        uint32_t& r2, uint32_t& r3, uint32_t addr) {
    asm volatile("ldmatrix.sync.aligned.m8n8.x4.shared.b16 {%0,%1,%2,%3}, [%4];"
                 : "=r"(r0), "=r"(r1), "=r"(r2), "=r"(r3) : "r"(addr));
}

__device__ __forceinline__ void ldsm_x4_trans(uint32_t& r0, uint32_t& r1,
                                              uint32_t& r2, uint32_t& r3, uint32_t addr) {
    asm volatile("ldmatrix.sync.aligned.m8n8.x4.trans.shared.b16 {%0,%1,%2,%3}, [%4];"
                 : "=r"(r0), "=r"(r1), "=r"(r2), "=r"(r3) : "r"(addr));
}

__device__ __forceinline__ uint32_t f2h2(float a, float b) {
    __half2 h = __floats2half2_rn(a, b);
    return *(uint32_t*)&h;
}

// ---------------- weight preconversion (vectorized) ---------------------------
__global__ void pack_qkv_w8(const float* __restrict__ Wq, const float* __restrict__ Wkv,
                            __half* __restrict__ dst) {
    int i = blockIdx.x * blockDim.x + threadIdx.x;
    const int NC8 = Dc / 8;
    if (i >= Lc * QKVSTR * NC8) return;
    int c8 = (i % NC8) * 8;
    int r  = (i / NC8) % QKVSTR;
    int l  = i / (NC8 * QKVSTR);
    const float* src;
    float sc;
    if (r < Dc) { src = Wq  + ((size_t)l * Dc + r) * Dc + c8;              sc = 0.125f; }
    else        { src = Wkv + ((size_t)l * 2 * Dc + (r - Dc)) * Dc + c8;   sc = 1.f; }
    float4 x = *(const float4*)src;
    float4 y = *(const float4*)(src + 4);
    __half2 o[4];
    o[0] = __floats2half2_rn(x.x * sc, x.y * sc);
    o[1] = __floats2half2_rn(x.z * sc, x.w * sc);
    o[2] = __floats2half2_rn(y.x * sc, y.y * sc);
    o[3] = __floats2half2_rn(y.z * sc, y.w * sc);
    *(uint4*)&dst[(size_t)i * 8] = *(uint4*)o;
}

__global__ void cvt_w8(const float* __restrict__ src, __half* __restrict__ dst, int n8) {
    int i = blockIdx.x * blockDim.x + threadIdx.x;
    if (i >= n8) return;
    float4 x = *(const float4*)(src + (size_t)i * 8);
    float4 y = *(const float4*)(src + (size_t)i * 8 + 4);
    __half2 o[4];
    o[0] = __floats2half2_rn(x.x, x.y);
    o[1] = __floats2half2_rn(x.z, x.w);
    o[2] = __floats2half2_rn(y.x, y.y);
    o[3] = __floats2half2_rn(y.z, y.w);
    *(uint4*)&dst[(size_t)i * 8] = *(uint4*)o;
}

// ---------------- embedding (4 elems/thread) ----------------
__global__ void embed_kernel(const int* __restrict__ data,
                             const float* __restrict__ we,
                             const float* __restrict__ pe,
                             float* __restrict__ h, __half* __restrict__ ht) {
    int i = blockIdx.x * blockDim.x + threadIdx.x;
    if (i >= M_ROWS * Dc / 4) return;
    int d4  = (i % (Dc / 4)) * 4;
    int row = i / (Dc / 4);
    int s   = row % Sc;
    int tok = data[row];
    float4 a = *(const float4*)(we + (size_t)tok * Dc + d4);
    float4 p = *(const float4*)(pe + (size_t)s   * Dc + d4);
    float4 v = make_float4(a.x + p.x, a.y + p.y, a.z + p.z, a.w + p.w);
    *(float4*)&h[(size_t)row * Dc + d4] = v;
    __half2 o[2];
    o[0] = __floats2half2_rn(v.x, v.y);
    o[1] = __floats2half2_rn(v.z, v.w);
    *(uint2*)&ht[(size_t)row * Dc + d4] = *(uint2*)o;
}

// ============ tgemm64: TBM=64, TBN=128, 3-stage pipeline, 1 sync/iter =========
// N-bound safe (works for N=10000 logits tail blocks); N must be even.
#define T2M 64
#define T2N 128
#define T2K 32
#define TP 40

__global__ __launch_bounds__(256) void tgemm64_kernel(
    const __half* __restrict__ A, const __half* __restrict__ W,
    const float* __restrict__ bias, const float* __restrict__ res,
    void* __restrict__ Cv, int M, int N, int K, int doRelu, int outMode)
{
    __shared__ __align__(16) __half As[3][T2M][TP];
    __shared__ __align__(16) __half Bs[3][T2N][TP];

    const int tid  = threadIdx.x;
    const int lane = tid & 31;
    const int warp = tid >> 5;
    const int wm   = warp >> 2;
    const int wn   = warp & 3;
    const int bm   = blockIdx.y * T2M;
    const int bn   = blockIdx.x * T2N;

    const uint32_t asBase = (uint32_t)__cvta_generic_to_shared(&As[0][0][0]);
    const uint32_t bsBase = (uint32_t)__cvta_generic_to_shared(&Bs[0][0][0]);

    float acc[2][4][4];
    #pragma unroll
    for (int i = 0; i < 2; i++)
        #pragma unroll
        for (int j = 0; j < 4; j++)
            #pragma unroll
            for (int t = 0; t < 4; t++) acc[i][j][t] = 0.f;

    const int KT = K / T2K;
    const int rA  = tid >> 2, hA = (tid & 3) * 8;

    #pragma unroll
    for (int s = 0; s < 2; s++) {
        int k0 = s * T2K;
        cp16(&As[s][rA][hA], A + (size_t)(bm + rA) * K + k0 + hA, 16);
        #pragma unroll
        for (int p = 0; p < 2; p++) {
            int c = tid + p * 256;
            int r = c >> 2, hf = (c & 3) * 8;
            int gn = bn + r;
            int ok = (gn < N) ? 16 : 0;
            int gc = (gn < N) ? gn : (N - 1);
            cp16(&Bs[s][r][hf], W + (size_t)gc * K + k0 + hf, ok);
        }
        asm volatile("cp.async.commit_group;\n");
    }

    const int r8  = lane & 7;
    const int sel = lane >> 3;

    for (int t = 0; t < KT; t++) {
        asm volatile("cp.async.wait_group 1;\n");
        __syncthreads();

        {
            int tp = t + 2;
            if (tp < KT) {
                int sb = tp % 3;
                int k0 = tp * T2K;
                cp16(&As[sb][rA][hA], A + (size_t)(bm + rA) * K + k0 + hA, 16);
                #pragma unroll
                for (int p = 0; p < 2; p++) {
                    int c = tid + p * 256;
                    int r = c >> 2, hf = (c & 3) * 8;
                    int gn = bn + r;
                    int ok = (gn < N) ? 16 : 0;
                    int gc = (gn < N) ? gn : (N - 1);
                    cp16(&Bs[sb][r][hf], W + (size_t)gc * K + k0 + hf, ok);
                }
            }
            asm volatile("cp.async.commit_group;\n");
        }

        const int buf = t % 3;
        #pragma unroll
        for (int ks = 0; ks < 2; ks++) {
            const int kb = ks * 16;
            uint32_t af[2][4], bf[4][2];
            #pragma unroll
            for (int mi = 0; mi < 2; mi++) {
                int row  = wm * 32 + mi * 16 + r8 + ((sel & 1) << 3);
                int colh = kb + ((sel >> 1) << 3);
                uint32_t addr = asBase + (((buf * T2M + row) * TP + colh) << 1);
                ldsm_x4(af[mi][0], af[mi][1], af[mi][2], af[mi][3], addr);
            }
            #pragma unroll
            for (int nj = 0; nj < 2; nj++) {
                int row  = wn * 32 + nj * 16 + r8 + ((sel >> 1) << 3);
                int colh = kb + ((sel & 1) << 3);
                uint32_t addr = bsBase + (((buf * T2N + row) * TP + colh) << 1);
                ldsm_x4(bf[nj*2][0], bf[nj*2][1], bf[nj*2+1][0], bf[nj*2+1][1], addr);
            }
            #pragma unroll
            for (int mi = 0; mi < 2; mi++)
                #pragma unroll
                for (int ni = 0; ni < 4; ni++)
                    mma_f16(acc[mi][ni], af[mi][0], af[mi][1], af[mi][2], af[mi][3],
                            bf[ni][0], bf[ni][1]);
        }
    }

    const int lr = lane >> 2;
    const int lc = (lane & 3) * 2;
    #pragma unroll
    for (int mi = 0; mi < 2; mi++) {
        int r0 = bm + wm * 32 + mi * 16 + lr;
        #pragma unroll
        for (int ni = 0; ni < 4; ni++) {
            int c0 = bn + wn * 32 + ni * 8 + lc;
            if (c0 >= N) continue;   // N even => c0+1 < N when c0 < N
            float v0 = acc[mi][ni][0], v1 = acc[mi][ni][1];
            float v2 = acc[mi][ni][2], v3 = acc[mi][ni][3];
            if (bias) {
                float b0 = bias[c0], b1 = bias[c0 + 1];
                v0 += b0; v1 += b1; v2 += b0; v3 += b1;
            }
            if (res) {
                v0 += res[(size_t)r0 * N + c0];
                v1 += res[(size_t)r0 * N + c0 + 1];
                v2 += res[(size_t)(r0 + 8) * N + c0];
                v3 += res[(size_t)(r0 + 8) * N + c0 + 1];
            }
            if (doRelu) {
                v0 = fmaxf(v0, 0.f); v1 = fmaxf(v1, 0.f);
                v2 = fmaxf(v2, 0.f); v3 = fmaxf(v3, 0.f);
            }
            if (outMode == 0) {
                float* C = (float*)Cv;
                *(float2*)&C[(size_t)r0 * N + c0]       = make_float2(v0, v1);
                *(float2*)&C[(size_t)(r0 + 8) * N + c0] = make_float2(v2, v3);
            } else {
                __half* C = (__half*)Cv;
                *(__half2*)&C[(size_t)r0 * N + c0]       = __floats2half2_rn(v0, v1);
                *(__half2*)&C[(size_t)(r0 + 8) * N + c0] = __floats2half2_rn(v2, v3);
            }
        }
    }
}

// ---------------- fp16 flash attention: balanced pairs, ldsm everywhere -------
#define APH 72
#define NT64 (Sc/64)
#define FATTN_SMEM ((64 + 128 + 128) * APH * 2)

extern __shared__ __half attn_smem[];

__global__ __launch_bounds__(128) void fattn_tc(
    const __half* __restrict__ Q, const __half* __restrict__ Kb,
    const __half* __restrict__ Vb, __half* __restrict__ O)
{
    __half* Qs = attn_smem;               // [64][APH]
    __half* Ks = Qs + 64 * APH;           // 2 x [64][APH]
    __half* Vk = Ks + 2 * 64 * APH;       // 2 x [64][APH]

    const int qpair = blockIdx.x;         // 0..7
    const int h  = blockIdx.y, b = blockIdx.z;
    const int tid  = threadIdx.x;
    const int lane = tid & 31;
    const int warp = tid >> 5;            // 0..3

    const int OST = Hc * DHc;

    const int r0   = warp * 16 + (lane >> 2);
    const int r8   = lane & 7;
    const int sel  = lane >> 3;
    const uint32_t qsBase = (uint32_t)__cvta_generic_to_shared(Qs);
    const uint32_t ksBase = (uint32_t)__cvta_generic_to_shared(Ks);
    const uint32_t vkBase = (uint32_t)__cvta_generic_to_shared(Vk);

    const size_t kvrow0 = (size_t)(b * Sc) * QKVSTR + h * DHc;

    const int vrow = ((lane >> 3) & 1) * 8 + (lane & 7);
    const int vsel = lane >> 4;

    #pragma unroll
    for (int seg = 0; seg < 2; seg++) {
        const int qt = seg ? (NT64 - 1 - qpair) : qpair;
        const int q0 = qt * 64;

        __syncthreads();

        #pragma unroll
        for (int p = 0; p < 4; p++) {
            int c = tid + p * 128;
            int r = c >> 3, d8 = (c & 7) * 8;
            float4 v = *(const float4*)(Q + (size_t)(b * Sc + q0 + r) * QKVSTR + h * DHc + d8);
            *(float4*)&Qs[r * APH + d8] = v;
        }

        #pragma unroll
        for (int p = 0; p < 4; p++) {
            int c = tid + p * 128;
            int r = c >> 3, d8 = (c & 7) * 8;
            cp16(&Ks[r * APH + d8], Kb + kvrow0 + (size_t)r * QKVSTR + d8, 16);
            cp16(&Vk[r * APH + d8], Vb + kvrow0 + (size_t)r * QKVSTR + d8, 16);
        }
        asm volatile("cp.async.commit_group;\n");

        __syncthreads();

        uint32_t qf[4][4];
        #pragma unroll
        for (int ks = 0; ks < 4; ks++) {
            int row  = warp * 16 + r8 + ((sel & 1) << 3);
            int colh = ks * 16 + ((sel >> 1) << 3);
            ldsm_x4(qf[ks][0], qf[ks][1], qf[ks][2], qf[ks][3],
                    qsBase + ((row * APH + colh) << 1));
        }

        float o_acc[8][4];
        #pragma unroll
        for (int n = 0; n < 8; n++)
            #pragma unroll
            for (int t = 0; t < 4; t++) o_acc[n][t] = 0.f;
        float m0 = -1e30f, m1 = -1e30f, l0 = 0.f, l1 = 0.f;

        const int nt = qt + 1;

        for (int kt = 0; kt < nt; kt++) {
            asm volatile("cp.async.wait_group 0;\n");
            __syncthreads();

            const int buf = kt & 1;
            if (kt + 1 < nt) {
                const int nb = buf ^ 1;
                const size_t base = kvrow0 + (size_t)(kt + 1) * 64 * QKVSTR;
                #pragma unroll
                for (int p = 0; p < 4; p++) {
                    int c = tid + p * 128;
                    int r = c >> 3, d8 = (c & 7) * 8;
                    cp16(&Ks[nb * 64 * APH + r * APH + d8], Kb + base + (size_t)r * QKVSTR + d8, 16);
                    cp16(&Vk[nb * 64 * APH + r * APH + d8], Vb + base + (size_t)r * QKVSTR + d8, 16);
                }
            }
            asm volatile("cp.async.commit_group;\n");

            const uint32_t ktBase = ksBase + ((buf * 64 * APH) << 1);
            const uint32_t vtBase = vkBase + ((buf * 64 * APH) << 1);

            float sacc[8][4];
            #pragma unroll
            for (int n = 0; n < 8; n++)
                #pragma unroll
                for (int t = 0; t < 4; t++) sacc[n][t] = 0.f;

            #pragma unroll
            for (int ks = 0; ks < 4; ks++) {
                const int kb = ks * 16;
                #pragma unroll
                for (int ng = 0; ng < 4; ng++) {
                    int row  = ng * 16 + r8 + ((sel >> 1) << 3);
                    int colh = kb + ((sel & 1) << 3);
                    uint32_t b00, b01, b10, b11;
                    ldsm_x4(b00, b01, b10, b11, ktBase + ((row * APH + colh) << 1));
                    mma_f16(sacc[2*ng],   qf[ks][0], qf[ks][1], qf[ks][2], qf[ks][3], b00, b01);
                    mma_f16(sacc[2*ng+1], qf[ks][0], qf[ks][1], qf[ks][2], qf[ks][3], b10, b11);
                }
            }

            if (kt == qt) {
                #pragma unroll
                for (int n = 0; n < 8; n++) {
                    const int c0 = n * 8 + (lane & 3) * 2;
                    if (c0     > r0)     sacc[n][0] = -1e30f;
                    if (c0 + 1 > r0)     sacc[n][1] = -1e30f;
                    if (c0     > r0 + 8) sacc[n][2] = -1e30f;
                    if (c0 + 1 > r0 + 8) sacc[n][3] = -1e30f;
                }
            }

            float mx0 = -1e30f, mx1 = -1e30f;
            #pragma unroll
            for (int n = 0; n < 8; n++) {
                mx0 = fmaxf(mx0, fmaxf(sacc[n][0], sacc[n][1]));
                mx1 = fmaxf(mx1, fmaxf(sacc[n][2], sacc[n][3]));
            }
            mx0 = fmaxf(mx0, __shfl_xor_sync(0xffffffffu, mx0, 1));
            mx0 = fmaxf(mx0, __shfl_xor_sync(0xffffffffu, mx0, 2));
            mx1 = fmaxf(mx1, __shfl_xor_sync(0xffffffffu, mx1, 1));
            mx1 = fmaxf(mx1, __shfl_xor_sync(0xffffffffu, mx1, 2));

            const float mn0 = fmaxf(m0, mx0);
            const float mn1 = fmaxf(m1, mx1);
            const float cr0 = __expf(m0 - mn0);
            const float cr1 = __expf(m1 - mn1);
            float s0 = 0.f, s1 = 0.f;
            #pragma unroll
            for (int n = 0; n < 8; n++) {
                float p00 = __expf(sacc[n][0] - mn0);
                float p01 = __expf(sacc[n][1] - mn0);
                float p10 = __expf(sacc[n][2] - mn1);
                float p11 = __expf(sacc[n][3] - mn1);
                s0 += p00 + p01;
                s1 += p10 + p11;
                sacc[n][0] = p00; sacc[n][1] = p01;
                sacc[n][2] = p10; sacc[n][3] = p11;
            }
            s0 += __shfl_xor_sync(0xffffffffu, s0, 1);
            s0 += __shfl_xor_sync(0xffffffffu, s0, 2);
            s1 += __shfl_xor_sync(0xffffffffu, s1, 1);
            s1 += __shfl_xor_sync(0xffffffffu, s1, 2);

            l0 = l0 * cr0 + s0;  m0 = mn0;
            l1 = l1 * cr1 + s1;  m1 = mn1;
            #pragma unroll
            for (int n = 0; n < 8; n++) {
                o_acc[n][0] *= cr0; o_acc[n][1] *= cr0;
                o_acc[n][2] *= cr1; o_acc[n][3] *= cr1;
            }

            #pragma unroll
            for (int j = 0; j < 4; j++) {
                const int kb = j * 16;
                uint32_t a0 = f2h2(sacc[2*j][0],   sacc[2*j][1]);
                uint32_t a1 = f2h2(sacc[2*j][2],   sacc[2*j][3]);
                uint32_t a2 = f2h2(sacc[2*j+1][0], sacc[2*j+1][1]);
                uint32_t a3 = f2h2(sacc[2*j+1][2], sacc[2*j+1][3]);
                #pragma unroll
                for (int n2 = 0; n2 < 4; n2++) {
                    const int row  = kb + vrow;
                    const int col8 = (n2 * 2 + vsel) * 8;
                    uint32_t b0, b1, b2, b3;
                    ldsm_x4_trans(b0, b1, b2, b3, vtBase + ((row * APH + col8) << 1));
                    mma_f16(o_acc[2*n2],   a0, a1, a2, a3, b0, b1);
                    mma_f16(o_acc[2*n2+1], a0, a1, a2, a3, b2, b3);
                }
            }
        }

        const float inv0 = 1.f / l0;
        const float inv1 = 1.f / l1;
        #pragma unroll
        for (int n = 0; n < 8; n++) {
            const int c0 = n * 8 + (lane & 3) * 2;
            size_t o0 = (size_t)(b * Sc + q0 + r0)     * OST + h * DHc + c0;
            size_t o1 = (size_t)(b * Sc + q0 + r0 + 8) * OST + h * DHc + c0;
            *(__half2*)&O[o0] = __floats2half2_rn(o_acc[n][0] * inv0, o_acc[n][1] * inv0);
            *(__half2*)&O[o1] = __floats2half2_rn(o_acc[n][2] * inv1, o_acc[n][3] * inv1);
        }
    }
}

// ---------------- LayerNorm over D=512 (single-pass reduction) ----------------
__global__ void ln_kernel(const float* __restrict__ X, const float* __restrict__ g,
                          const float* __restrict__ bta, float* __restrict__ Y,
                          __half* __restrict__ Yt) {
    int row = blockIdx.x;
    const float* x = X + (size_t)row * Dc;
    float*  y  = Y  + (size_t)row * Dc;
    __half* yt = Yt + (size_t)row * Dc;
    int tid = threadIdx.x;
    int d0  = tid * 4;

    float4 v = *(const float4*)(x + d0);
    float sum = v.x + v.y + v.z + v.w;
    float sq  = v.x*v.x + v.y*v.y + v.z*v.z + v.w*v.w;

    __shared__ float redS[4], redQ[4];
    #pragma unroll
    for (int off = 16; off; off >>= 1) {
        sum += __shfl_xor_sync(0xffffffffu, sum, off);
        sq  += __shfl_xor_sync(0xffffffffu, sq,  off);
    }
    if ((tid & 31) == 0) { redS[tid >> 5] = sum; redQ[tid >> 5] = sq; }
    __syncthreads();
    sum = redS[0] + redS[1] + redS[2] + redS[3];
    sq  = redQ[0] + redQ[1] + redQ[2] + redQ[3];
    float mean = sum * (1.f / Dc);
    float var  = sq * (1.f / Dc) - mean * mean;
    float rstd = rsqrtf(var + 1e-5f);

    float4 gg = *(const float4*)(g + d0);
    float4 bb = *(const float4*)(bta + d0);
    float4 o;
    o.x = (v.x - mean) * rstd * gg.x + bb.x;
    o.y = (v.y - mean) * rstd * gg.y + bb.y;
    o.z = (v.z - mean) * rstd * gg.z + bb.z;
    o.w = (v.w - mean) * rstd * gg.w + bb.w;
    *(float4*)(y + d0) = o;
    __half2 ho[2];
    ho[0] = __floats2half2_rn(o.x, o.y);
    ho[1] = __floats2half2_rn(o.z, o.w);
    *(uint2*)(yt + d0) = *(uint2*)ho;
}

// ---------------- launch ----------------------------------------------------
extern "C" void kernel_launch(void* const* d_in, const int* in_sizes, int n_in,
                              void* d_out, int out_size) {
    const int*   data = (const int*)  d_in[0];
    const float* we   = (const float*)d_in[1];
    const float* pe   = (const float*)d_in[2];
    const float* Wq   = (const float*)d_in[3];
    const float* Wkv  = (const float*)d_in[4];
    const float* Wo   = (const float*)d_in[5];
    const float* g1   = (const float*)d_in[6];
    const float* bl1  = (const float*)d_in[7];
    const float* W1   = (const float*)d_in[8];
    const float* bf1  = (const float*)d_in[9];
    const float* W2   = (const float*)d_in[10];
    const float* bf2  = (const float*)d_in[11];
    const float* g2   = (const float*)d_in[12];
    const float* bl2  = (const float*)d_in[13];
    const float* outb = (const float*)d_in[14];
    float* out = (float*)d_out;

    float *h, *tmp;
    __half *ht, *qkv, *aot, *fft;
    __half *wqkv, *wo_t, *w1_t, *w2_t, *we_t;
    cudaGetSymbolAddress((void**)&h,    g_h);
    cudaGetSymbolAddress((void**)&ht,   g_ht);
    cudaGetSymbolAddress((void**)&qkv,  g_qkv);
    cudaGetSymbolAddress((void**)&aot,  g_aot);
    cudaGetSymbolAddress((void**)&tmp,  g_tmp);
    cudaGetSymbolAddress((void**)&fft,  g_fft);
    cudaGetSymbolAddress((void**)&wqkv, g_wqkv);
    cudaGetSymbolAddress((void**)&wo_t, g_wo_t);
    cudaGetSymbolAddress((void**)&w1_t, g_w1_t);
    cudaGetSymbolAddress((void**)&w2_t, g_w2_t);
    cudaGetSymbolAddress((void**)&we_t, g_we_t);

    cudaFuncSetAttribute(fattn_tc, cudaFuncAttributeMaxDynamicSharedMemorySize, FATTN_SMEM);

    {
        int n8;
        n8 = Lc * QKVSTR * Dc / 8;  pack_qkv_w8<<<(n8 + 255)/256, 256>>>(Wq, Wkv, wqkv);
        n8 = Lc * Dc * Dc / 8;      cvt_w8<<<(n8 + 255)/256, 256>>>(Wo, wo_t, n8);
        n8 = Lc * DIc * Dc / 8;     cvt_w8<<<(n8 + 255)/256, 256>>>(W1, w1_t, n8);
        n8 = Lc * Dc * DIc / 8;     cvt_w8<<<(n8 + 255)/256, 256>>>(W2, w2_t, n8);
        n8 = Vc * Dc / 8;           cvt_w8<<<(n8 + 255)/256, 256>>>(we, we_t, n8);
    }

    embed_kernel<<<(M_ROWS*Dc/4 + 255)/256, 256>>>(data, we, pe, h, ht);

    dim3 g64D  ( Dc/128,     M_ROWS/64);
    dim3 g64QKV( QKVSTR/128, M_ROWS/64);
    dim3 g64DI ( DIc/128,    M_ROWS/64);
    dim3 g64V  ((Vc + 127)/128, M_ROWS/64);    // (79, 64) logits
    dim3 gsA   (NT64/2, Hc, Bc);

    for (int l = 0; l < Lc; l++) {
        tgemm64_kernel<<<g64QKV, 256>>>(ht, wqkv + (size_t)l*QKVSTR*Dc, nullptr, nullptr,
                                        qkv, M_ROWS, QKVSTR, Dc, 0, 1);

        fattn_tc<<<gsA, 128, FATTN_SMEM>>>(qkv, qkv + Dc, qkv + 2*Dc, aot);

        tgemm64_kernel<<<g64D, 256>>>(aot, wo_t + (size_t)l*Dc*Dc, nullptr, h, tmp,
                                      M_ROWS, Dc, Dc, 0, 0);
        ln_kernel<<<M_ROWS, 128>>>(tmp, g1 + (size_t)l*Dc, bl1 + (size_t)l*Dc, h, ht);

        tgemm64_kernel<<<g64DI, 256>>>(ht, w1_t + (size_t)l*DIc*Dc, bf1 + (size_t)l*DIc, nullptr,
                                       fft, M_ROWS, DIc, Dc, 1, 1);
        tgemm64_kernel<<<g64D, 256>>>(fft, w2_t + (size_t)l*Dc*DIc, bf2 + (size_t)l*Dc, h,
                                      tmp, M_ROWS, Dc, DIc, 0, 0);
        ln_kernel<<<M_ROWS, 128>>>(tmp, g2 + (size_t)l*Dc, bl2 + (size_t)l*Dc, h, ht);
    }

    tgemm64_kernel<<<g64V, 256>>>(ht, we_t, outb, nullptr, out, M_ROWS, Vc, Dc, 0, 0);
}

// round 17
// speedup vs baseline: 1.1391x; 1.0013x over previous
#include <cuda_runtime.h>
#include <cuda_fp16.h>
#include <math.h>
#include <stdint.h>

#define Bc 4
#define Sc 1024
#define Dc 512
#define Hc 8
#define DHc 64
#define DIc 2048
#define Lc 12
#define Vc 10000
#define M_ROWS (Bc*Sc)   /* 4096 */
#define QKVSTR (3*Dc)    /* 1536 */

// ---------------- scratch (no allocations allowed) ----------------
__device__ float  g_h   [M_ROWS*Dc];
__device__ __half g_ht  [M_ROWS*Dc];
__device__ __half g_qkv [M_ROWS*QKVSTR];
__device__ __half g_aot [M_ROWS*Dc];
__device__ float  g_tmp [M_ROWS*Dc];
__device__ __half g_fft [M_ROWS*DIc];
__device__ __half g_wqkv[Lc*QKVSTR*Dc];
__device__ __half g_wo_t[Lc*Dc*Dc];
__device__ __half g_w1_t[Lc*DIc*Dc];
__device__ __half g_w2_t[Lc*Dc*DIc];
__device__ __half g_we_t[Vc*Dc];

// ---------------- helpers ----------------------------------------------------
__device__ __forceinline__ void cp16(void* smem, const void* g, int srcBytes) {
    uint32_t s = (uint32_t)__cvta_generic_to_shared(smem);
    asm volatile("cp.async.cg.shared.global [%0], [%1], 16, %2;\n"
                 :: "r"(s), "l"(g), "r"(srcBytes));
}

__device__ __forceinline__ void mma_f16(float c[4],
    uint32_t a0, uint32_t a1, uint32_t a2, uint32_t a3,
    uint32_t b0, uint32_t b1)
{
    asm volatile(
        "mma.sync.aligned.m16n8k16.row.col.f32.f16.f16.f32 "
        "{%0,%1,%2,%3}, {%4,%5,%6,%7}, {%8,%9}, {%0,%1,%2,%3};"
        : "+f"(c[0]), "+f"(c[1]), "+f"(c[2]), "+f"(c[3])
        : "r"(a0), "r"(a1), "r"(a2), "r"(a3), "r"(b0), "r"(b1));
}

__device__ __forceinline__ void ldsm_x4(uint32_t& r0, uint32_t& r1,
                                        uint32_t& r2, uint32_t& r3, uint32_t addr) {
    asm volatile("ldmatrix.sync.aligned.m8n8.x4.shared.b16 {%0,%1,%2,%3}, [%4];"
                 : "=r"(r0), "=r"(r1), "=r"(r2), "=r"(r3) : "r"(addr));
}

__device__ __forceinline__ void ldsm_x4_trans(uint32_t& r0, uint32_t& r1,
                                              uint32_t& r2, uint32_t& r3, uint32_t addr) {
    asm volatile("ldmatrix.sync.aligned.m8n8.x4.trans.shared.b16 {%0,%1,%2,%3}, [%4];"
                 : "=r"(r0), "=r"(r1), "=r"(r2), "=r"(r3) : "r"(addr));
}

__device__ __forceinline__ uint32_t f2h2(float a, float b) {
    __half2 h = __floats2half2_rn(a, b);
    return *(uint32_t*)&h;
}

// ---------------- fused weight preconversion (single launch) ------------------
#define N8_QKV (Lc*QKVSTR*Dc/8)
#define N8_WO  (Lc*Dc*Dc/8)
#define N8_W1  (Lc*DIc*Dc/8)
#define N8_W2  (Lc*Dc*DIc/8)
#define N8_WE  (Vc*Dc/8)
#define N8_ALL (N8_QKV + N8_WO + N8_W1 + N8_W2 + N8_WE)

__global__ void pack_all_w8(const float* __restrict__ Wq, const float* __restrict__ Wkv,
                            const float* __restrict__ Wo, const float* __restrict__ W1,
                            const float* __restrict__ W2, const float* __restrict__ we,
                            __half* __restrict__ wqkv, __half* __restrict__ wo_t,
                            __half* __restrict__ w1_t, __half* __restrict__ w2_t,
                            __half* __restrict__ we_t)
{
    int i = blockIdx.x * blockDim.x + threadIdx.x;
    if (i >= N8_ALL) return;

    const float* src;
    __half* dst;
    float sc = 1.f;
    if (i < N8_QKV) {
        // packed QKV: row r in [0,1536): 0..511 = Wq*0.125, rest Wkv
        const int NC8 = Dc / 8;
        int c8 = (i % NC8) * 8;
        int r  = (i / NC8) % QKVSTR;
        int l  = i / (NC8 * QKVSTR);
        if (r < Dc) { src = Wq  + ((size_t)l * Dc + r) * Dc + c8;            sc = 0.125f; }
        else        { src = Wkv + ((size_t)l * 2 * Dc + (r - Dc)) * Dc + c8; }
        dst = wqkv + (size_t)i * 8;
    } else if (i < N8_QKV + N8_WO) {
        int j = i - N8_QKV;
        src = Wo + (size_t)j * 8;  dst = wo_t + (size_t)j * 8;
    } else if (i < N8_QKV + N8_WO + N8_W1) {
        int j = i - N8_QKV - N8_WO;
        src = W1 + (size_t)j * 8;  dst = w1_t + (size_t)j * 8;
    } else if (i < N8_QKV + N8_WO + N8_W1 + N8_W2) {
        int j = i - N8_QKV - N8_WO - N8_W1;
        src = W2 + (size_t)j * 8;  dst = w2_t + (size_t)j * 8;
    } else {
        int j = i - N8_QKV - N8_WO - N8_W1 - N8_W2;
        src = we + (size_t)j * 8;  dst = we_t + (size_t)j * 8;
    }

    float4 x = *(const float4*)src;
    float4 y = *(const float4*)(src + 4);
    __half2 o[4];
    o[0] = __floats2half2_rn(x.x * sc, x.y * sc);
    o[1] = __floats2half2_rn(x.z * sc, x.w * sc);
    o[2] = __floats2half2_rn(y.x * sc, y.y * sc);
    o[3] = __floats2half2_rn(y.z * sc, y.w * sc);
    *(uint4*)dst = *(uint4*)o;
}

// ---------------- embedding (4 elems/thread) ----------------
__global__ void embed_kernel(const int* __restrict__ data,
                             const float* __restrict__ we,
                             const float* __restrict__ pe,
                             float* __restrict__ h, __half* __restrict__ ht) {
    int i = blockIdx.x * blockDim.x + threadIdx.x;
    if (i >= M_ROWS * Dc / 4) return;
    int d4  = (i % (Dc / 4)) * 4;
    int row = i / (Dc / 4);
    int s   = row % Sc;
    int tok = data[row];
    float4 a = *(const float4*)(we + (size_t)tok * Dc + d4);
    float4 p = *(const float4*)(pe + (size_t)s   * Dc + d4);
    float4 v = make_float4(a.x + p.x, a.y + p.y, a.z + p.z, a.w + p.w);
    *(float4*)&h[(size_t)row * Dc + d4] = v;
    __half2 o[2];
    o[0] = __floats2half2_rn(v.x, v.y);
    o[1] = __floats2half2_rn(v.z, v.w);
    *(uint2*)&ht[(size_t)row * Dc + d4] = *(uint2*)o;
}

// ============ tgemm64: TBM=64, TBN=128, 3-stage pipeline, 3 CTAs/SM ==========
// N-bound safe (logits tail); N must be even.
#define T2M 64
#define T2N 128
#define T2K 32
#define TP 40

__global__ __launch_bounds__(256, 3) void tgemm64_kernel(
    const __half* __restrict__ A, const __half* __restrict__ W,
    const float* __restrict__ bias, const float* __restrict__ res,
    void* __restrict__ Cv, int M, int N, int K, int doRelu, int outMode)
{
    __shared__ __align__(16) __half As[3][T2M][TP];
    __shared__ __align__(16) __half Bs[3][T2N][TP];

    const int tid  = threadIdx.x;
    const int lane = tid & 31;
    const int warp = tid >> 5;
    const int wm   = warp >> 2;
    const int wn   = warp & 3;
    const int bm   = blockIdx.y * T2M;
    const int bn   = blockIdx.x * T2N;

    const uint32_t asBase = (uint32_t)__cvta_generic_to_shared(&As[0][0][0]);
    const uint32_t bsBase = (uint32_t)__cvta_generic_to_shared(&Bs[0][0][0]);

    float acc[2][4][4];
    #pragma unroll
    for (int i = 0; i < 2; i++)
        #pragma unroll
        for (int j = 0; j < 4; j++)
            #pragma unroll
            for (int t = 0; t < 4; t++) acc[i][j][t] = 0.f;

    const int KT = K / T2K;
    const int rA  = tid >> 2, hA = (tid & 3) * 8;

    #pragma unroll
    for (int s = 0; s < 2; s++) {
        int k0 = s * T2K;
        cp16(&As[s][rA][hA], A + (size_t)(bm + rA) * K + k0 + hA, 16);
        #pragma unroll
        for (int p = 0; p < 2; p++) {
            int c = tid + p * 256;
            int r = c >> 2, hf = (c & 3) * 8;
            int gn = bn + r;
            int ok = (gn < N) ? 16 : 0;
            int gc = (gn < N) ? gn : (N - 1);
            cp16(&Bs[s][r][hf], W + (size_t)gc * K + k0 + hf, ok);
        }
        asm volatile("cp.async.commit_group;\n");
    }

    const int r8  = lane & 7;
    const int sel = lane >> 3;

    for (int t = 0; t < KT; t++) {
        asm volatile("cp.async.wait_group 1;\n");
        __syncthreads();

        {
            int tp = t + 2;
            if (tp < KT) {
                int sb = tp % 3;
                int k0 = tp * T2K;
                cp16(&As[sb][rA][hA], A + (size_t)(bm + rA) * K + k0 + hA, 16);
                #pragma unroll
                for (int p = 0; p < 2; p++) {
                    int c = tid + p * 256;
                    int r = c >> 2, hf = (c & 3) * 8;
                    int gn = bn + r;
                    int ok = (gn < N) ? 16 : 0;
                    int gc = (gn < N) ? gn : (N - 1);
                    cp16(&Bs[sb][r][hf], W + (size_t)gc * K + k0 + hf, ok);
                }
            }
            asm volatile("cp.async.commit_group;\n");
        }

        const int buf = t % 3;
        #pragma unroll
        for (int ks = 0; ks < 2; ks++) {
            const int kb = ks * 16;
            uint32_t af[2][4], bf[4][2];
            #pragma unroll
            for (int mi = 0; mi < 2; mi++) {
                int row  = wm * 32 + mi * 16 + r8 + ((sel & 1) << 3);
                int colh = kb + ((sel >> 1) << 3);
                uint32_t addr = asBase + (((buf * T2M + row) * TP + colh) << 1);
                ldsm_x4(af[mi][0], af[mi][1], af[mi][2], af[mi][3], addr);
            }
            #pragma unroll
            for (int nj = 0; nj < 2; nj++) {
                int row  = wn * 32 + nj * 16 + r8 + ((sel >> 1) << 3);
                int colh = kb + ((sel & 1) << 3);
                uint32_t addr = bsBase + (((buf * T2N + row) * TP + colh) << 1);
                ldsm_x4(bf[nj*2][0], bf[nj*2][1], bf[nj*2+1][0], bf[nj*2+1][1], addr);
            }
            #pragma unroll
            for (int mi = 0; mi < 2; mi++)
                #pragma unroll
                for (int ni = 0; ni < 4; ni++)
                    mma_f16(acc[mi][ni], af[mi][0], af[mi][1], af[mi][2], af[mi][3],
                            bf[ni][0], bf[ni][1]);
        }
    }

    const int lr = lane >> 2;
    const int lc = (lane & 3) * 2;
    #pragma unroll
    for (int mi = 0; mi < 2; mi++) {
        int r0 = bm + wm * 32 + mi * 16 + lr;
        #pragma unroll
        for (int ni = 0; ni < 4; ni++) {
            int c0 = bn + wn * 32 + ni * 8 + lc;
            if (c0 >= N) continue;   // N even => c0+1 < N when c0 < N
            float v0 = acc[mi][ni][0], v1 = acc[mi][ni][1];
            float v2 = acc[mi][ni][2], v3 = acc[mi][ni][3];
            if (bias) {
                float b0 = bias[c0], b1 = bias[c0 + 1];
                v0 += b0; v1 += b1; v2 += b0; v3 += b1;
            }
            if (res) {
                v0 += res[(size_t)r0 * N + c0];
                v1 += res[(size_t)r0 * N + c0 + 1];
                v2 += res[(size_t)(r0 + 8) * N + c0];
                v3 += res[(size_t)(r0 + 8) * N + c0 + 1];
            }
            if (doRelu) {
                v0 = fmaxf(v0, 0.f); v1 = fmaxf(v1, 0.f);
                v2 = fmaxf(v2, 0.f); v3 = fmaxf(v3, 0.f);
            }
            if (outMode == 0) {
                float* C = (float*)Cv;
                *(float2*)&C[(size_t)r0 * N + c0]       = make_float2(v0, v1);
                *(float2*)&C[(size_t)(r0 + 8) * N + c0] = make_float2(v2, v3);
            } else {
                __half* C = (__half*)Cv;
                *(__half2*)&C[(size_t)r0 * N + c0]       = __floats2half2_rn(v0, v1);
                *(__half2*)&C[(size_t)(r0 + 8) * N + c0] = __floats2half2_rn(v2, v3);
            }
        }
    }
}

// ---------------- fp16 flash attention: balanced pairs, ldsm everywhere -------
#define APH 72
#define NT64 (Sc/64)
#define FATTN_SMEM ((64 + 128 + 128) * APH * 2)

extern __shared__ __half attn_smem[];

__global__ __launch_bounds__(128) void fattn_tc(
    const __half* __restrict__ Q, const __half* __restrict__ Kb,
    const __half* __restrict__ Vb, __half* __restrict__ O)
{
    __half* Qs = attn_smem;               // [64][APH]
    __half* Ks = Qs + 64 * APH;           // 2 x [64][APH]
    __half* Vk = Ks + 2 * 64 * APH;       // 2 x [64][APH]

    const int qpair = blockIdx.x;         // 0..7
    const int h  = blockIdx.y, b = blockIdx.z;
    const int tid  = threadIdx.x;
    const int lane = tid & 31;
    const int warp = tid >> 5;            // 0..3

    const int OST = Hc * DHc;

    const int r0   = warp * 16 + (lane >> 2);
    const int r8   = lane & 7;
    const int sel  = lane >> 3;
    const uint32_t qsBase = (uint32_t)__cvta_generic_to_shared(Qs);
    const uint32_t ksBase = (uint32_t)__cvta_generic_to_shared(Ks);
    const uint32_t vkBase = (uint32_t)__cvta_generic_to_shared(Vk);

    const size_t kvrow0 = (size_t)(b * Sc) * QKVSTR + h * DHc;

    const int vrow = ((lane >> 3) & 1) * 8 + (lane & 7);
    const int vsel = lane >> 4;

    #pragma unroll
    for (int seg = 0; seg < 2; seg++) {
        const int qt = seg ? (NT64 - 1 - qpair) : qpair;
        const int q0 = qt * 64;

        __syncthreads();

        #pragma unroll
        for (int p = 0; p < 4; p++) {
            int c = tid + p * 128;
            int r = c >> 3, d8 = (c & 7) * 8;
            float4 v = *(const float4*)(Q + (size_t)(b * Sc + q0 + r) * QKVSTR + h * DHc + d8);
            *(float4*)&Qs[r * APH + d8] = v;
        }

        #pragma unroll
        for (int p = 0; p < 4; p++) {
            int c = tid + p * 128;
            int r = c >> 3, d8 = (c & 7) * 8;
            cp16(&Ks[r * APH + d8], Kb + kvrow0 + (size_t)r * QKVSTR + d8, 16);
            cp16(&Vk[r * APH + d8], Vb + kvrow0 + (size_t)r * QKVSTR + d8, 16);
        }
        asm volatile("cp.async.commit_group;\n");

        __syncthreads();

        uint32_t qf[4][4];
        #pragma unroll
        for (int ks = 0; ks < 4; ks++) {
            int row  = warp * 16 + r8 + ((sel & 1) << 3);
            int colh = ks * 16 + ((sel >> 1) << 3);
            ldsm_x4(qf[ks][0], qf[ks][1], qf[ks][2], qf[ks][3],
                    qsBase + ((row * APH + colh) << 1));
        }

        float o_acc[8][4];
        #pragma unroll
        for (int n = 0; n < 8; n++)
            #pragma unroll
            for (int t = 0; t < 4; t++) o_acc[n][t] = 0.f;
        float m0 = -1e30f, m1 = -1e30f, l0 = 0.f, l1 = 0.f;

        const int nt = qt + 1;

        for (int kt = 0; kt < nt; kt++) {
            asm volatile("cp.async.wait_group 0;\n");
            __syncthreads();

            const int buf = kt & 1;
            if (kt + 1 < nt) {
                const int nb = buf ^ 1;
                const size_t base = kvrow0 + (size_t)(kt + 1) * 64 * QKVSTR;
                #pragma unroll
                for (int p = 0; p < 4; p++) {
                    int c = tid + p * 128;
                    int r = c >> 3, d8 = (c & 7) * 8;
                    cp16(&Ks[nb * 64 * APH + r * APH + d8], Kb + base + (size_t)r * QKVSTR + d8, 16);
                    cp16(&Vk[nb * 64 * APH + r * APH + d8], Vb + base + (size_t)r * QKVSTR + d8, 16);
                }
            }
            asm volatile("cp.async.commit_group;\n");

            const uint32_t ktBase = ksBase + ((buf * 64 * APH) << 1);
            const uint32_t vtBase = vkBase + ((buf * 64 * APH) << 1);

            float sacc[8][4];
            #pragma unroll
            for (int n = 0; n < 8; n++)
                #pragma unroll
                for (int t = 0; t < 4; t++) sacc[n][t] = 0.f;

            #pragma unroll
            for (int ks = 0; ks < 4; ks++) {
                const int kb = ks * 16;
                #pragma unroll
                for (int ng = 0; ng < 4; ng++) {
                    int row  = ng * 16 + r8 + ((sel >> 1) << 3);
                    int colh = kb + ((sel & 1) << 3);
                    uint32_t b00, b01, b10, b11;
                    ldsm_x4(b00, b01, b10, b11, ktBase + ((row * APH + colh) << 1));
                    mma_f16(sacc[2*ng],   qf[ks][0], qf[ks][1], qf[ks][2], qf[ks][3], b00, b01);
                    mma_f16(sacc[2*ng+1], qf[ks][0], qf[ks][1], qf[ks][2], qf[ks][3], b10, b11);
                }
            }

            if (kt == qt) {
                #pragma unroll
                for (int n = 0; n < 8; n++) {
                    const int c0 = n * 8 + (lane & 3) * 2;
                    if (c0     > r0)     sacc[n][0] = -1e30f;
                    if (c0 + 1 > r0)     sacc[n][1] = -1e30f;
                    if (c0     > r0 + 8) sacc[n][2] = -1e30f;
                    if (c0 + 1 > r0 + 8) sacc[n][3] = -1e30f;
                }
            }

            float mx0 = -1e30f, mx1 = -1e30f;
            #pragma unroll
            for (int n = 0; n < 8; n++) {
                mx0 = fmaxf(mx0, fmaxf(sacc[n][0], sacc[n][1]));
                mx1 = fmaxf(mx1, fmaxf(sacc[n][2], sacc[n][3]));
            }
            mx0 = fmaxf(mx0, __shfl_xor_sync(0xffffffffu, mx0, 1));
            mx0 = fmaxf(mx0, __shfl_xor_sync(0xffffffffu, mx0, 2));
            mx1 = fmaxf(mx1, __shfl_xor_sync(0xffffffffu, mx1, 1));
            mx1 = fmaxf(mx1, __shfl_xor_sync(0xffffffffu, mx1, 2));

            const float mn0 = fmaxf(m0, mx0);
            const float mn1 = fmaxf(m1, mx1);
            const float cr0 = __expf(m0 - mn0);
            const float cr1 = __expf(m1 - mn1);
            float s0 = 0.f, s1 = 0.f;
            #pragma unroll
            for (int n = 0; n < 8; n++) {
                float p00 = __expf(sacc[n][0] - mn0);
                float p01 = __expf(sacc[n][1] - mn0);
                float p10 = __expf(sacc[n][2] - mn1);
                float p11 = __expf(sacc[n][3] - mn1);
                s0 += p00 + p01;
                s1 += p10 + p11;
                sacc[n][0] = p00; sacc[n][1] = p01;
                sacc[n][2] = p10; sacc[n][3] = p11;
            }
            s0 += __shfl_xor_sync(0xffffffffu, s0, 1);
            s0 += __shfl_xor_sync(0xffffffffu, s0, 2);
            s1 += __shfl_xor_sync(0xffffffffu, s1, 1);
            s1 += __shfl_xor_sync(0xffffffffu, s1, 2);

            l0 = l0 * cr0 + s0;  m0 = mn0;
            l1 = l1 * cr1 + s1;  m1 = mn1;
            #pragma unroll
            for (int n = 0; n < 8; n++) {
                o_acc[n][0] *= cr0; o_acc[n][1] *= cr0;
                o_acc[n][2] *= cr1; o_acc[n][3] *= cr1;
            }

            #pragma unroll
            for (int j = 0; j < 4; j++) {
                const int kb = j * 16;
                uint32_t a0 = f2h2(sacc[2*j][0],   sacc[2*j][1]);
                uint32_t a1 = f2h2(sacc[2*j][2],   sacc[2*j][3]);
                uint32_t a2 = f2h2(sacc[2*j+1][0], sacc[2*j+1][1]);
                uint32_t a3 = f2h2(sacc[2*j+1][2], sacc[2*j+1][3]);
                #pragma unroll
                for (int n2 = 0; n2 < 4; n2++) {
                    const int row  = kb + vrow;
                    const int col8 = (n2 * 2 + vsel) * 8;
                    uint32_t b0, b1, b2, b3;
                    ldsm_x4_trans(b0, b1, b2, b3, vtBase + ((row * APH + col8) << 1));
                    mma_f16(o_acc[2*n2],   a0, a1, a2, a3, b0, b1);
                    mma_f16(o_acc[2*n2+1], a0, a1, a2, a3, b2, b3);
                }
            }
        }

        const float inv0 = 1.f / l0;
        const float inv1 = 1.f / l1;
        #pragma unroll
        for (int n = 0; n < 8; n++) {
            const int c0 = n * 8 + (lane & 3) * 2;
            size_t o0 = (size_t)(b * Sc + q0 + r0)     * OST + h * DHc + c0;
            size_t o1 = (size_t)(b * Sc + q0 + r0 + 8) * OST + h * DHc + c0;
            *(__half2*)&O[o0] = __floats2half2_rn(o_acc[n][0] * inv0, o_acc[n][1] * inv0);
            *(__half2*)&O[o1] = __floats2half2_rn(o_acc[n][2] * inv1, o_acc[n][3] * inv1);
        }
    }
}

// ---------------- LayerNorm: 2 rows per block (256 threads) -------------------
__global__ void ln_kernel(const float* __restrict__ X, const float* __restrict__ g,
                          const float* __restrict__ bta, float* __restrict__ Y,
                          __half* __restrict__ Yt) {
    int half = threadIdx.x >> 7;           // 0..1 (row select)
    int tid  = threadIdx.x & 127;
    int row  = blockIdx.x * 2 + half;
    const float* x = X + (size_t)row * Dc;
    float*  y  = Y  + (size_t)row * Dc;
    __half* yt = Yt + (size_t)row * Dc;
    int d0 = tid * 4;

    float4 v = *(const float4*)(x + d0);
    float sum = v.x + v.y + v.z + v.w;
    float sq  = v.x*v.x + v.y*v.y + v.z*v.z + v.w*v.w;

    __shared__ float redS[8], redQ[8];
    #pragma unroll
    for (int off = 16; off; off >>= 1) {
        sum += __shfl_xor_sync(0xffffffffu, sum, off);
        sq  += __shfl_xor_sync(0xffffffffu, sq,  off);
    }
    int wid = threadIdx.x >> 5;            // 0..7
    if ((threadIdx.x & 31) == 0) { redS[wid] = sum; redQ[wid] = sq; }
    __syncthreads();
    int base = half * 4;
    sum = redS[base] + redS[base+1] + redS[base+2] + redS[base+3];
    sq  = redQ[base] + redQ[base+1] + redQ[base+2] + redQ[base+3];
    float mean = sum * (1.f / Dc);
    float var  = sq * (1.f / Dc) - mean * mean;
    float rstd = rsqrtf(var + 1e-5f);

    float4 gg = *(const float4*)(g + d0);
    float4 bb = *(const float4*)(bta + d0);
    float4 o;
    o.x = (v.x - mean) * rstd * gg.x + bb.x;
    o.y = (v.y - mean) * rstd * gg.y + bb.y;
    o.z = (v.z - mean) * rstd * gg.z + bb.z;
    o.w = (v.w - mean) * rstd * gg.w + bb.w;
    *(float4*)(y + d0) = o;
    __half2 ho[2];
    ho[0] = __floats2half2_rn(o.x, o.y);
    ho[1] = __floats2half2_rn(o.z, o.w);
    *(uint2*)(yt + d0) = *(uint2*)ho;
}

// ---------------- launch ----------------------------------------------------
extern "C" void kernel_launch(void* const* d_in, const int* in_sizes, int n_in,
                              void* d_out, int out_size) {
    const int*   data = (const int*)  d_in[0];
    const float* we   = (const float*)d_in[1];
    const float* pe   = (const float*)d_in[2];
    const float* Wq   = (const float*)d_in[3];
    const float* Wkv  = (const float*)d_in[4];
    const float* Wo   = (const float*)d_in[5];
    const float* g1   = (const float*)d_in[6];
    const float* bl1  = (const float*)d_in[7];
    const float* W1   = (const float*)d_in[8];
    const float* bf1  = (const float*)d_in[9];
    const float* W2   = (const float*)d_in[10];
    const float* bf2  = (const float*)d_in[11];
    const float* g2   = (const float*)d_in[12];
    const float* bl2  = (const float*)d_in[13];
    const float* outb = (const float*)d_in[14];
    float* out = (float*)d_out;

    float *h, *tmp;
    __half *ht, *qkv, *aot, *fft;
    __half *wqkv, *wo_t, *w1_t, *w2_t, *we_t;
    cudaGetSymbolAddress((void**)&h,    g_h);
    cudaGetSymbolAddress((void**)&ht,   g_ht);
    cudaGetSymbolAddress((void**)&qkv,  g_qkv);
    cudaGetSymbolAddress((void**)&aot,  g_aot);
    cudaGetSymbolAddress((void**)&tmp,  g_tmp);
    cudaGetSymbolAddress((void**)&fft,  g_fft);
    cudaGetSymbolAddress((void**)&wqkv, g_wqkv);
    cudaGetSymbolAddress((void**)&wo_t, g_wo_t);
    cudaGetSymbolAddress((void**)&w1_t, g_w1_t);
    cudaGetSymbolAddress((void**)&w2_t, g_w2_t);
    cudaGetSymbolAddress((void**)&we_t, g_we_t);

    cudaFuncSetAttribute(fattn_tc, cudaFuncAttributeMaxDynamicSharedMemorySize, FATTN_SMEM);

    pack_all_w8<<<(N8_ALL + 255)/256, 256>>>(Wq, Wkv, Wo, W1, W2, we,
                                             wqkv, wo_t, w1_t, w2_t, we_t);

    embed_kernel<<<(M_ROWS*Dc/4 + 255)/256, 256>>>(data, we, pe, h, ht);

    dim3 g64D  ( Dc/128,     M_ROWS/64);
    dim3 g64QKV( QKVSTR/128, M_ROWS/64);
    dim3 g64DI ( DIc/128,    M_ROWS/64);
    dim3 g64V  ((Vc + 127)/128, M_ROWS/64);
    dim3 gsA   (NT64/2, Hc, Bc);

    for (int l = 0; l < Lc; l++) {
        tgemm64_kernel<<<g64QKV, 256>>>(ht, wqkv + (size_t)l*QKVSTR*Dc, nullptr, nullptr,
                                        qkv, M_ROWS, QKVSTR, Dc, 0, 1);

        fattn_tc<<<gsA, 128, FATTN_SMEM>>>(qkv, qkv + Dc, qkv + 2*Dc, aot);

        tgemm64_kernel<<<g64D, 256>>>(aot, wo_t + (size_t)l*Dc*Dc, nullptr, h, tmp,
                                      M_ROWS, Dc, Dc, 0, 0);
        ln_kernel<<<M_ROWS/2, 256>>>(tmp, g1 + (size_t)l*Dc, bl1 + (size_t)l*Dc, h, ht);

        tgemm64_kernel<<<g64DI, 256>>>(ht, w1_t + (size_t)l*DIc*Dc, bf1 + (size_t)l*DIc, nullptr,
                                       fft, M_ROWS, DIc, Dc, 1, 1);
        tgemm64_kernel<<<g64D, 256>>>(fft, w2_t + (size_t)l*Dc*DIc, bf2 + (size_t)l*Dc, h,
                                      tmp, M_ROWS, Dc, DIc, 0, 0);
        ln_kernel<<<M_ROWS/2, 256>>>(tmp, g2 + (size_t)l*Dc, bl2 + (size_t)l*Dc, h, ht);
    }

    tgemm64_kernel<<<g64V, 256>>>(ht, we_t, outb, nullptr, out, M_ROWS, Vc, Dc, 0, 0);
}